// round 6
// baseline (speedup 1.0000x reference)
#include <cuda_runtime.h>
#include <cuda_fp16.h>
#include <cstdint>

#define NEG_SLOPE 0.2f

static constexpr int MAXN = 50000;
static constexpr int MAXE = 800000;
static constexpr int CIN  = 128;
static constexpr int CHID = 256;
static constexpr int COUT = 128;
static constexpr int ED   = 8;

// ---------------- scratch (static device globals; no allocation allowed) ---
__device__ int    d_deg[MAXN];
__device__ int    d_row[MAXN + 1];
__device__ int    d_cur[MAXN];
__device__ int    d_csr_src[MAXE];
__device__ float  d_tmpa[MAXE];   // edge-ordered aev1
__device__ float  d_tmpb[MAXE];   // edge-ordered aev2
__device__ float  d_aev1[MAXE];   // CSR-ordered
__device__ float  d_aev2[MAXE];
__device__ float  d_alpha[MAXE];  // exp(leaky(logit)) per CSR edge
__device__ __half d_hh[(size_t)MAXN * CHID];    // fp16 transformed feats
__device__ float  d_hidden[(size_t)MAXN * CHID];
__device__ float  d_as1[MAXN];
__device__ float  d_ad1[MAXN];
__device__ float  d_as2[MAXN];
__device__ float  d_ad2[MAXN];
__device__ float  d_easum[ED];
__device__ float  d_v[2][ED];
__device__ float  d_loopae[2];

// ---------------- zero + compute v (MUST run with >=512 threads/block) -----
__global__ void zero_v_kernel(const float* __restrict__ We1,
                              const float* __restrict__ ae1,
                              const float* __restrict__ We2,
                              const float* __restrict__ ae2, int n) {
    for (int i = blockIdx.x * blockDim.x + threadIdx.x; i < n;
         i += gridDim.x * blockDim.x) {
        d_deg[i] = 0;
        d_as1[i] = 0.f; d_ad1[i] = 0.f;
        d_as2[i] = 0.f; d_ad2[i] = 0.f;
    }
    if (blockIdx.x == 0) {
        if (threadIdx.x < ED) d_easum[threadIdx.x] = 0.f;
        int wid = threadIdx.x >> 5, lane = threadIdx.x & 31;
        if (wid < ED) {
            float s = 0.f;
            for (int c = lane; c < CHID; c += 32) s += We1[wid * CHID + c] * ae1[c];
            for (int o = 16; o; o >>= 1) s += __shfl_xor_sync(~0u, s, o);
            if (!lane) d_v[0][wid] = s;
        } else if (wid < 2 * ED) {
            int r = wid - ED;
            float s = 0.f;
            for (int c = lane; c < COUT; c += 32) s += We2[r * COUT + c] * ae2[c];
            for (int o = 16; o; o >>= 1) s += __shfl_xor_sync(~0u, s, o);
            if (!lane) d_v[1][r] = s;
        }
    }
}

// histogram of dst degrees + easum + per-edge attr attention (both layers)
__global__ void hist_kernel(const int* __restrict__ dstp,
                            const float* __restrict__ ea, int E) {
    __shared__ float ss[ED];
    if (threadIdx.x < ED) ss[threadIdx.x] = 0.f;
    __syncthreads();
    float v1[ED], v2[ED];
#pragma unroll
    for (int k = 0; k < ED; k++) { v1[k] = d_v[0][k]; v2[k] = d_v[1][k]; }
    float ls[ED] = {};
    for (int i = blockIdx.x * blockDim.x + threadIdx.x; i < E;
         i += gridDim.x * blockDim.x) {
        atomicAdd(&d_deg[dstp[i]], 1);
        const float4* p = (const float4*)(ea + (size_t)i * ED);
        float4 a = p[0], b = p[1];
        ls[0] += a.x; ls[1] += a.y; ls[2] += a.z; ls[3] += a.w;
        ls[4] += b.x; ls[5] += b.y; ls[6] += b.z; ls[7] += b.w;
        d_tmpa[i] = a.x * v1[0] + a.y * v1[1] + a.z * v1[2] + a.w * v1[3] +
                    b.x * v1[4] + b.y * v1[5] + b.z * v1[6] + b.w * v1[7];
        d_tmpb[i] = a.x * v2[0] + a.y * v2[1] + a.z * v2[2] + a.w * v2[3] +
                    b.x * v2[4] + b.y * v2[5] + b.z * v2[6] + b.w * v2[7];
    }
#pragma unroll
    for (int k = 0; k < ED; k++) atomicAdd(&ss[k], ls[k]);
    __syncthreads();
    if (threadIdx.x < ED) atomicAdd(&d_easum[threadIdx.x], ss[threadIdx.x]);
}

// single-block exclusive scan of d_deg -> d_row / d_cur ; + loopae
__global__ void scan_kernel(int n, float Einv) {
    __shared__ int partial[1024];
    const int t = threadIdx.x;
    const int CHK = (n + 1023) / 1024;
    int start = t * CHK;
    int end = start + CHK; if (end > n) end = n;
    int s = 0;
    for (int i = start; i < end; i++) s += d_deg[i];
    partial[t] = s;
    __syncthreads();
    for (int off = 1; off < 1024; off <<= 1) {
        int v = (t >= off) ? partial[t - off] : 0;
        __syncthreads();
        partial[t] += v;
        __syncthreads();
    }
    int run = (t == 0) ? 0 : partial[t - 1];
    for (int i = start; i < end; i++) {
        d_row[i] = run;
        d_cur[i] = run;
        run += d_deg[i];
    }
    if (t == 1023) d_row[n] = partial[1023];
    if (t < 2) {
        float la = 0.f;
#pragma unroll
        for (int i = 0; i < ED; i++) la += d_easum[i] * Einv * d_v[t][i];
        d_loopae[t] = la;
    }
}

// scatter edges into CSR-by-dst; permute precomputed aev
__global__ void scatter_kernel(const int* __restrict__ srcp,
                               const int* __restrict__ dstp, int E) {
    for (int e = blockIdx.x * blockDim.x + threadIdx.x; e < E;
         e += gridDim.x * blockDim.x) {
        int d = dstp[e];
        int pos = atomicAdd(&d_cur[d], 1);
        d_csr_src[pos] = srcp[e];
        d_aev1[pos] = d_tmpa[e];
        d_aev2[pos] = d_tmpb[e];
    }
}

// ---------------- tf32 tensor-core GEMM (ldmatrix frags) + fused dots ------
__device__ __forceinline__ uint32_t f2tf32(float x) {
    uint32_t u;
    asm("cvt.rna.tf32.f32 %0, %1;" : "=r"(u) : "f"(x));
    return u;
}
__device__ __forceinline__ void mma_tf32(float* d, const uint32_t* a,
                                         const uint32_t* b) {
    asm volatile(
        "mma.sync.aligned.m16n8k8.row.col.f32.tf32.tf32.f32 "
        "{%0,%1,%2,%3}, {%4,%5,%6,%7}, {%8,%9}, {%0,%1,%2,%3};\n"
        : "+f"(d[0]), "+f"(d[1]), "+f"(d[2]), "+f"(d[3])
        : "r"(a[0]), "r"(a[1]), "r"(a[2]), "r"(a[3]), "r"(b[0]), "r"(b[1]));
}
__device__ __forceinline__ void ldsm_x4(uint32_t& r0, uint32_t& r1,
                                        uint32_t& r2, uint32_t& r3,
                                        uint32_t addr) {
    asm volatile(
        "ldmatrix.sync.aligned.m8n8.x4.shared.b16 {%0,%1,%2,%3}, [%4];"
        : "=r"(r0), "=r"(r1), "=r"(r2), "=r"(r3)
        : "r"(addr));
}

// Ch[M,N] = half(A[M,K] @ B[K,N]); fused fp32 dots:
// as_out[m] += sum_c C[m,c]*av[c], ad_out[m] += sum_c C[m,c]*dv[c]
template <int BM, int BN, int WM, int WN>
__global__ __launch_bounds__(256, 2) void mma_gemm_kernel(
    const float* __restrict__ A, const float* __restrict__ B,
    __half* __restrict__ Ch, const float* __restrict__ av,
    const float* __restrict__ dv, float* __restrict__ as_out,
    float* __restrict__ ad_out, int M, int N, int K) {
    constexpr int GBK = 16;
    constexpr int AP = GBK + 4;   // 20 words/row -> conflict-free ldmatrix
    constexpr int KP = GBK + 4;   // 20 words/row (B is n-major)
    constexpr int WCOLS = BN / WN;
    constexpr int MI = WM / 16;
    constexpr int NJ = WN / 8;
    constexpr int LA = BM / 64;

    __shared__ __align__(16) uint32_t As[2][BM][AP];   // [m][k]
    __shared__ __align__(16) uint32_t Bs[2][BN][KP];   // [n][k]

    const int t = threadIdx.x;
    const int bm = blockIdx.y * BM;
    const int bn = blockIdx.x * BN;
    const int warp = t >> 5, lane = t & 31;
    const int g = lane >> 2, t4 = lane & 3;
    const int wm = (warp / WCOLS) * WM, wn = (warp % WCOLS) * WN;

    // per-lane ldmatrix source addresses (A: m-rows; B: n-rows)
    const uint32_t aBase =
        (uint32_t)__cvta_generic_to_shared(&As[0][0][0]);
    const uint32_t bBase =
        (uint32_t)__cvta_generic_to_shared(&Bs[0][0][0]);
    const uint32_t aLane =
        aBase + (((wm + (lane & 15)) * AP + ((lane & 16) >> 2)) << 2);
    const uint32_t bLane =
        bBase +
        (((wn + (lane & 7) + ((lane & 16) >> 1)) * KP + ((lane & 8) >> 1))
         << 2);
    constexpr uint32_t AsBytes = BM * AP * 4;
    constexpr uint32_t BsBytes = BN * KP * 4;

    // gmem staging
    float4 pa[LA];
    float pbv[8];
    const int bn_n = t & (BN - 1);            // n within tile
    const int bkb = (t / BN) * 8;             // k base (0 or 8)

    auto ldg = [&](int k0) {
#pragma unroll
        for (int r = 0; r < LA; r++) {
            int id = t + 256 * r;
            int row = id >> 2, col = (id & 3) * 4;
            int gr = bm + row;
            pa[r] = (gr < M) ? *(const float4*)(A + (size_t)gr * K + k0 + col)
                             : make_float4(0.f, 0.f, 0.f, 0.f);
        }
#pragma unroll
        for (int c = 0; c < 8; c++)
            pbv[c] = B[(size_t)(k0 + bkb + c) * N + bn + bn_n];
    };
    auto sts = [&](int s) {
#pragma unroll
        for (int r = 0; r < LA; r++) {
            int id = t + 256 * r;
            int row = id >> 2, col = (id & 3) * 4;
            uint4 u;
            u.x = f2tf32(pa[r].x); u.y = f2tf32(pa[r].y);
            u.z = f2tf32(pa[r].z); u.w = f2tf32(pa[r].w);
            *(uint4*)&As[s][row][col] = u;
        }
        uint4 u0, u1;
        u0.x = f2tf32(pbv[0]); u0.y = f2tf32(pbv[1]);
        u0.z = f2tf32(pbv[2]); u0.w = f2tf32(pbv[3]);
        u1.x = f2tf32(pbv[4]); u1.y = f2tf32(pbv[5]);
        u1.z = f2tf32(pbv[6]); u1.w = f2tf32(pbv[7]);
        *(uint4*)&Bs[s][bn_n][bkb] = u0;
        *(uint4*)&Bs[s][bn_n][bkb + 4] = u1;
    };

    float acc[MI][NJ][4];
#pragma unroll
    for (int i = 0; i < MI; i++)
#pragma unroll
        for (int j = 0; j < NJ; j++)
#pragma unroll
            for (int r = 0; r < 4; r++) acc[i][j][r] = 0.f;

    const int nIter = K / GBK;
    ldg(0);
    sts(0);
    __syncthreads();

    for (int it = 0; it < nIter; it++) {
        const int s = it & 1;
        if (it + 1 < nIter) ldg((it + 1) * GBK);
        const uint32_t aBuf = aLane + s * AsBytes;
        const uint32_t bBuf = bLane + s * BsBytes;
#pragma unroll
        for (int kk = 0; kk < 2; kk++) {
            uint32_t af[MI][4], bf[NJ][2];
#pragma unroll
            for (int i = 0; i < MI; i++)
                ldsm_x4(af[i][0], af[i][1], af[i][2], af[i][3],
                        aBuf + kk * 32 + i * (16 * AP * 4));
#pragma unroll
            for (int j2 = 0; j2 < NJ / 2; j2++)
                ldsm_x4(bf[2 * j2][0], bf[2 * j2][1], bf[2 * j2 + 1][0],
                        bf[2 * j2 + 1][1],
                        bBuf + kk * 32 + j2 * (16 * KP * 4));
#pragma unroll
            for (int i = 0; i < MI; i++)
#pragma unroll
                for (int j = 0; j < NJ; j++) mma_tf32(acc[i][j], af[i], bf[j]);
        }
        if (it + 1 < nIter) {
            sts(s ^ 1);
            __syncthreads();
        }
    }

    // epilogue: half store + fused partial dots into as/ad via atomics
#pragma unroll
    for (int i = 0; i < MI; i++) {
        int r0 = bm + wm + i * 16 + g;
        int r1 = r0 + 8;
        float s0 = 0.f, d0 = 0.f, s1 = 0.f, d1 = 0.f;
#pragma unroll
        for (int j = 0; j < NJ; j++) {
            int c = bn + wn + j * 8 + 2 * t4;
            float a0 = av[c], a1 = av[c + 1];
            float e0 = dv[c], e1 = dv[c + 1];
            s0 += acc[i][j][0] * a0 + acc[i][j][1] * a1;
            d0 += acc[i][j][0] * e0 + acc[i][j][1] * e1;
            s1 += acc[i][j][2] * a0 + acc[i][j][3] * a1;
            d1 += acc[i][j][2] * e0 + acc[i][j][3] * e1;
            if (r0 < M)
                *(__half2*)(Ch + (size_t)r0 * N + c) =
                    __floats2half2_rn(acc[i][j][0], acc[i][j][1]);
            if (r1 < M)
                *(__half2*)(Ch + (size_t)r1 * N + c) =
                    __floats2half2_rn(acc[i][j][2], acc[i][j][3]);
        }
#pragma unroll
        for (int o = 1; o < 4; o <<= 1) {
            s0 += __shfl_xor_sync(~0u, s0, o);
            d0 += __shfl_xor_sync(~0u, d0, o);
            s1 += __shfl_xor_sync(~0u, s1, o);
            d1 += __shfl_xor_sync(~0u, d1, o);
        }
        if (t4 == 0) {
            if (r0 < M) {
                atomicAdd(&as_out[r0], s0);
                atomicAdd(&ad_out[r0], d0);
            }
            if (r1 < M) {
                atomicAdd(&as_out[r1], s1);
                atomicAdd(&ad_out[r1], d1);
            }
        }
    }
}

__device__ __forceinline__ float leaky(float x) {
    return fmaxf(x, NEG_SLOPE * x);
}

// -------- warp-per-node fused alpha + softmax + fp16 gather aggregation ----
template <int C, bool RELU>
__global__ void aggregate_kernel(const __half* __restrict__ hh,
                                 const float* __restrict__ bias,
                                 float* __restrict__ out,
                                 const float* __restrict__ asv,
                                 const float* __restrict__ adv,
                                 const float* __restrict__ aev, int N,
                                 int layer) {
    int warp = (blockIdx.x * blockDim.x + threadIdx.x) >> 5;
    int lane = threadIdx.x & 31;
    if (warp >= N) return;
    const int n = warp;
    const int rs = d_row[n], re = d_row[n + 1];
    const float adn = adv[n];
    float eself = __expf(leaky(asv[n] + adn + d_loopae[layer]));
    // pass 1: per-edge exp(leaky(logit)), lane-parallel; logits are O(1)
    float ssum = 0.f;
    for (int j = rs + lane; j < re; j += 32) {
        int s = d_csr_src[j];
        float ex = __expf(leaky(asv[s] + aev[j] + adn));
        d_alpha[j] = ex;
        ssum += ex;
    }
    for (int o = 16; o; o >>= 1) ssum += __shfl_xor_sync(~0u, ssum, o);
    __syncwarp();  // fence d_alpha stores before cross-lane reads
    float inv = 1.f / (ssum + eself);

    constexpr int NH2 = C / 64;  // half2 per lane (4 for C=256, 2 for C=128)
    float acc[2 * NH2];
    union U4 { uint4 v; __half2 h2[4]; };
    union U2 { uint2 v; __half2 h2[2]; };

    auto accum = [&](int s, float w) {
        if constexpr (C == 256) {
            U4 r; r.v = ((const uint4*)(hh + (size_t)s * C))[lane];
#pragma unroll
            for (int k = 0; k < 4; k++) {
                float2 f = __half22float2(r.h2[k]);
                acc[2 * k] += w * f.x;
                acc[2 * k + 1] += w * f.y;
            }
        } else {
            U2 r; r.v = ((const uint2*)(hh + (size_t)s * C))[lane];
#pragma unroll
            for (int k = 0; k < 2; k++) {
                float2 f = __half22float2(r.h2[k]);
                acc[2 * k] += w * f.x;
                acc[2 * k + 1] += w * f.y;
            }
        }
    };

#pragma unroll
    for (int k = 0; k < 2 * NH2; k++) acc[k] = 0.f;
    accum(n, eself * inv);  // self loop

    // 4x unrolled edge loop -> gather MLP=4
    int j = rs;
    for (; j + 4 <= re; j += 4) {
        float w0 = d_alpha[j] * inv, w1 = d_alpha[j + 1] * inv;
        float w2 = d_alpha[j + 2] * inv, w3 = d_alpha[j + 3] * inv;
        int s0 = d_csr_src[j], s1 = d_csr_src[j + 1];
        int s2 = d_csr_src[j + 2], s3 = d_csr_src[j + 3];
        if constexpr (C == 256) {
            U4 r0, r1, r2, r3;
            r0.v = ((const uint4*)(hh + (size_t)s0 * C))[lane];
            r1.v = ((const uint4*)(hh + (size_t)s1 * C))[lane];
            r2.v = ((const uint4*)(hh + (size_t)s2 * C))[lane];
            r3.v = ((const uint4*)(hh + (size_t)s3 * C))[lane];
#pragma unroll
            for (int k = 0; k < 4; k++) {
                float2 f0 = __half22float2(r0.h2[k]);
                float2 f1 = __half22float2(r1.h2[k]);
                float2 f2 = __half22float2(r2.h2[k]);
                float2 f3 = __half22float2(r3.h2[k]);
                acc[2 * k] += w0 * f0.x + w1 * f1.x + w2 * f2.x + w3 * f3.x;
                acc[2 * k + 1] +=
                    w0 * f0.y + w1 * f1.y + w2 * f2.y + w3 * f3.y;
            }
        } else {
            U2 r0, r1, r2, r3;
            r0.v = ((const uint2*)(hh + (size_t)s0 * C))[lane];
            r1.v = ((const uint2*)(hh + (size_t)s1 * C))[lane];
            r2.v = ((const uint2*)(hh + (size_t)s2 * C))[lane];
            r3.v = ((const uint2*)(hh + (size_t)s3 * C))[lane];
#pragma unroll
            for (int k = 0; k < 2; k++) {
                float2 f0 = __half22float2(r0.h2[k]);
                float2 f1 = __half22float2(r1.h2[k]);
                float2 f2 = __half22float2(r2.h2[k]);
                float2 f3 = __half22float2(r3.h2[k]);
                acc[2 * k] += w0 * f0.x + w1 * f1.x + w2 * f2.x + w3 * f3.x;
                acc[2 * k + 1] +=
                    w0 * f0.y + w1 * f1.y + w2 * f2.y + w3 * f3.y;
            }
        }
    }
    for (; j < re; j++) accum(d_csr_src[j], d_alpha[j] * inv);

    // write out: lane owns columns [lane*2*NH2, +2*NH2)
    const int base = lane * 2 * NH2;
    float* op = out + (size_t)n * C + base;
    const float* bp = bias + base;
#pragma unroll
    for (int k = 0; k < 2 * NH2; k += 4) {
        float4 b = *(const float4*)(bp + k);
        float4 o = make_float4(acc[k] + b.x, acc[k + 1] + b.y,
                               acc[k + 2] + b.z, acc[k + 3] + b.w);
        if (RELU) {
            o.x = fmaxf(o.x, 0.f);
            o.y = fmaxf(o.y, 0.f);
            o.z = fmaxf(o.z, 0.f);
            o.w = fmaxf(o.w, 0.f);
        }
        *(float4*)(op + k) = o;
    }
}

// ---------------- launch ----------------------------------------------------
extern "C" void kernel_launch(void* const* d_in, const int* in_sizes, int n_in,
                              void* d_out, int out_size) {
    const float* x   = (const float*)d_in[0];
    const int*   ei  = (const int*)d_in[1];
    const float* ea  = (const float*)d_in[2];
    const float* W1  = (const float*)d_in[3];
    const float* We1 = (const float*)d_in[4];
    const float* as1 = (const float*)d_in[5];
    const float* ad1 = (const float*)d_in[6];
    const float* ae1 = (const float*)d_in[7];
    const float* b1  = (const float*)d_in[8];
    const float* W2  = (const float*)d_in[9];
    const float* We2 = (const float*)d_in[10];
    const float* as2 = (const float*)d_in[11];
    const float* ad2 = (const float*)d_in[12];
    const float* ae2 = (const float*)d_in[13];
    const float* b2  = (const float*)d_in[14];
    float* out = (float*)d_out;

    const int E = in_sizes[2] / ED;
    const int N = in_sizes[0] / CIN;
    const int* srcp = ei;
    const int* dstp = ei + E;

    void* p;
    cudaGetSymbolAddress(&p, d_hh);     __half* hhp   = (__half*)p;
    cudaGetSymbolAddress(&p, d_hidden); float* hidbuf = (float*)p;
    cudaGetSymbolAddress(&p, d_aev1);   float* aev1p  = (float*)p;
    cudaGetSymbolAddress(&p, d_aev2);   float* aev2p  = (float*)p;
    cudaGetSymbolAddress(&p, d_as1);    float* as1p   = (float*)p;
    cudaGetSymbolAddress(&p, d_ad1);    float* ad1p   = (float*)p;
    cudaGetSymbolAddress(&p, d_as2);    float* as2p   = (float*)p;
    cudaGetSymbolAddress(&p, d_ad2);    float* ad2p   = (float*)p;

    const int TPB = 256;
    const int warpsPerBlock = TPB / 32;
    const int nodeBlocks = (N + warpsPerBlock - 1) / warpsPerBlock;
    const int edgeBlocks = (E + TPB - 1) / TPB;   // 1 edge/thread

    // 1-3: structure build prologue (zero_v NEEDS 512 threads: 16 warps for v)
    zero_v_kernel<<<128, 512>>>(We1, ae1, We2, ae2, N);
    hist_kernel<<<edgeBlocks, TPB>>>(dstp, ea, E);
    scan_kernel<<<1, 1024>>>(N, 1.f / (float)E);

    // 4: layer-1 GEMM (+fused dots, half output) — 4th launch for ncu
    {
        dim3 g(CHID / 128, (N + 127) / 128);
        mma_gemm_kernel<128, 128, 64, 32><<<g, 256>>>(
            x, W1, hhp, as1, ad1, as1p, ad1p, N, CHID, CIN);
    }
    // 5: CSR scatter (independent of GEMM)
    scatter_kernel<<<edgeBlocks, TPB>>>(srcp, dstp, E);

    // 6: layer-1 fused alpha+softmax+aggregate (fp16 gather)
    aggregate_kernel<CHID, true><<<nodeBlocks, TPB>>>(hhp, b1, hidbuf, as1p,
                                                      ad1p, aev1p, N, 0);

    // 7: layer-2 GEMM (+fused dots, half output)
    {
        dim3 g(COUT / 128, (N + 63) / 64);
        mma_gemm_kernel<64, 128, 32, 32><<<g, 256>>>(
            hidbuf, W2, hhp, as2, ad2, as2p, ad2p, N, COUT, CHID);
    }
    // 8: layer-2 fused aggregate
    aggregate_kernel<COUT, false><<<nodeBlocks, TPB>>>(hhp, b2, out, as2p,
                                                       ad2p, aev2p, N, 1);
}

// round 7
// speedup vs baseline: 1.4741x; 1.4741x over previous
#include <cuda_runtime.h>
#include <cuda_fp16.h>
#include <cstdint>

#define NEG_SLOPE 0.2f

static constexpr int MAXN = 50000;
static constexpr int MAXE = 800000;
static constexpr int CIN  = 128;
static constexpr int CHID = 256;
static constexpr int COUT = 128;
static constexpr int ED   = 8;

// ---------------- scratch (static device globals; no allocation allowed) ---
__device__ int    d_deg[MAXN];
__device__ int    d_row[MAXN + 1];
__device__ int    d_cur[MAXN];
__device__ int    d_csr_src[MAXE];
__device__ float  d_tmpa[MAXE];   // edge-ordered aev1
__device__ float  d_tmpb[MAXE];   // edge-ordered aev2
__device__ float  d_aev1[MAXE];   // CSR-ordered
__device__ float  d_aev2[MAXE];
__device__ float  d_alpha[MAXE];  // exp(leaky(logit)) per CSR edge
__device__ __half d_hh[(size_t)MAXN * CHID];    // fp16 transformed feats
__device__ float  d_hidden[(size_t)MAXN * CHID];
__device__ float  d_as1[MAXN];
__device__ float  d_ad1[MAXN];
__device__ float  d_as2[MAXN];
__device__ float  d_ad2[MAXN];
__device__ float  d_easum[ED];
__device__ float  d_v[2][ED];
__device__ float  d_loopae[2];

// ---------------- zero + compute v (MUST run with >=512 threads/block) -----
__global__ void zero_v_kernel(const float* __restrict__ We1,
                              const float* __restrict__ ae1,
                              const float* __restrict__ We2,
                              const float* __restrict__ ae2, int n) {
    for (int i = blockIdx.x * blockDim.x + threadIdx.x; i < n;
         i += gridDim.x * blockDim.x) {
        d_deg[i] = 0;
        d_as1[i] = 0.f; d_ad1[i] = 0.f;
        d_as2[i] = 0.f; d_ad2[i] = 0.f;
    }
    if (blockIdx.x == 0) {
        if (threadIdx.x < ED) d_easum[threadIdx.x] = 0.f;
        int wid = threadIdx.x >> 5, lane = threadIdx.x & 31;
        if (wid < ED) {
            float s = 0.f;
            for (int c = lane; c < CHID; c += 32) s += We1[wid * CHID + c] * ae1[c];
            for (int o = 16; o; o >>= 1) s += __shfl_xor_sync(~0u, s, o);
            if (!lane) d_v[0][wid] = s;
        } else if (wid < 2 * ED) {
            int r = wid - ED;
            float s = 0.f;
            for (int c = lane; c < COUT; c += 32) s += We2[r * COUT + c] * ae2[c];
            for (int o = 16; o; o >>= 1) s += __shfl_xor_sync(~0u, s, o);
            if (!lane) d_v[1][r] = s;
        }
    }
}

// histogram of dst degrees + easum + per-edge attr attention (both layers)
// grid-stride with ~6 edges/thread: local ls[] accumulate, ONE atomics pass
__global__ void hist_kernel(const int* __restrict__ dstp,
                            const float* __restrict__ ea, int E) {
    __shared__ float ss[ED];
    if (threadIdx.x < ED) ss[threadIdx.x] = 0.f;
    __syncthreads();
    float v1[ED], v2[ED];
#pragma unroll
    for (int k = 0; k < ED; k++) { v1[k] = d_v[0][k]; v2[k] = d_v[1][k]; }
    float ls[ED] = {};
    for (int i = blockIdx.x * blockDim.x + threadIdx.x; i < E;
         i += gridDim.x * blockDim.x) {
        atomicAdd(&d_deg[dstp[i]], 1);
        const float4* p = (const float4*)(ea + (size_t)i * ED);
        float4 a = p[0], b = p[1];
        ls[0] += a.x; ls[1] += a.y; ls[2] += a.z; ls[3] += a.w;
        ls[4] += b.x; ls[5] += b.y; ls[6] += b.z; ls[7] += b.w;
        d_tmpa[i] = a.x * v1[0] + a.y * v1[1] + a.z * v1[2] + a.w * v1[3] +
                    b.x * v1[4] + b.y * v1[5] + b.z * v1[6] + b.w * v1[7];
        d_tmpb[i] = a.x * v2[0] + a.y * v2[1] + a.z * v2[2] + a.w * v2[3] +
                    b.x * v2[4] + b.y * v2[5] + b.z * v2[6] + b.w * v2[7];
    }
#pragma unroll
    for (int k = 0; k < ED; k++) atomicAdd(&ss[k], ls[k]);
    __syncthreads();
    if (threadIdx.x < ED) atomicAdd(&d_easum[threadIdx.x], ss[threadIdx.x]);
}

// single-block exclusive scan of d_deg -> d_row / d_cur ; + loopae
__global__ void scan_kernel(int n, float Einv) {
    __shared__ int partial[1024];
    const int t = threadIdx.x;
    const int CHK = (n + 1023) / 1024;
    int start = t * CHK;
    int end = start + CHK; if (end > n) end = n;
    int s = 0;
    for (int i = start; i < end; i++) s += d_deg[i];
    partial[t] = s;
    __syncthreads();
    for (int off = 1; off < 1024; off <<= 1) {
        int v = (t >= off) ? partial[t - off] : 0;
        __syncthreads();
        partial[t] += v;
        __syncthreads();
    }
    int run = (t == 0) ? 0 : partial[t - 1];
    for (int i = start; i < end; i++) {
        d_row[i] = run;
        d_cur[i] = run;
        run += d_deg[i];
    }
    if (t == 1023) d_row[n] = partial[1023];
    if (t < 2) {
        float la = 0.f;
#pragma unroll
        for (int i = 0; i < ED; i++) la += d_easum[i] * Einv * d_v[t][i];
        d_loopae[t] = la;
    }
}

// scatter edges into CSR-by-dst; permute precomputed aev (grid-stride)
__global__ void scatter_kernel(const int* __restrict__ srcp,
                               const int* __restrict__ dstp, int E) {
    for (int e = blockIdx.x * blockDim.x + threadIdx.x; e < E;
         e += gridDim.x * blockDim.x) {
        int d = dstp[e];
        int pos = atomicAdd(&d_cur[d], 1);
        d_csr_src[pos] = srcp[e];
        d_aev1[pos] = d_tmpa[e];
        d_aev2[pos] = d_tmpb[e];
    }
}

// ---------------- tf32 tensor-core GEMM (ldmatrix frags) + fused dots ------
__device__ __forceinline__ uint32_t f2tf32(float x) {
    uint32_t u;
    asm("cvt.rna.tf32.f32 %0, %1;" : "=r"(u) : "f"(x));
    return u;
}
__device__ __forceinline__ void mma_tf32(float* d, const uint32_t* a,
                                         const uint32_t* b) {
    asm volatile(
        "mma.sync.aligned.m16n8k8.row.col.f32.tf32.tf32.f32 "
        "{%0,%1,%2,%3}, {%4,%5,%6,%7}, {%8,%9}, {%0,%1,%2,%3};\n"
        : "+f"(d[0]), "+f"(d[1]), "+f"(d[2]), "+f"(d[3])
        : "r"(a[0]), "r"(a[1]), "r"(a[2]), "r"(a[3]), "r"(b[0]), "r"(b[1]));
}
__device__ __forceinline__ void ldsm_x4(uint32_t& r0, uint32_t& r1,
                                        uint32_t& r2, uint32_t& r3,
                                        uint32_t addr) {
    asm volatile(
        "ldmatrix.sync.aligned.m8n8.x4.shared.b16 {%0,%1,%2,%3}, [%4];"
        : "=r"(r0), "=r"(r1), "=r"(r2), "=r"(r3)
        : "r"(addr));
}

// Ch[M,N] = half(A[M,K] @ B[K,N]); fused fp32 dots:
// as_out[m] += sum_c C[m,c]*av[c], ad_out[m] += sum_c C[m,c]*dv[c]
template <int BM, int BN, int WM, int WN>
__global__ __launch_bounds__(256, 2) void mma_gemm_kernel(
    const float* __restrict__ A, const float* __restrict__ B,
    __half* __restrict__ Ch, const float* __restrict__ av,
    const float* __restrict__ dv, float* __restrict__ as_out,
    float* __restrict__ ad_out, int M, int N, int K) {
    constexpr int GBK = 16;
    constexpr int AP = GBK + 4;   // 20 words/row -> conflict-free ldmatrix
    constexpr int KP = GBK + 4;   // 20 words/row (B is n-major)
    constexpr int WCOLS = BN / WN;
    constexpr int MI = WM / 16;
    constexpr int NJ = WN / 8;
    constexpr int LA = BM / 64;

    __shared__ __align__(16) uint32_t As[2][BM][AP];   // [m][k]
    __shared__ __align__(16) uint32_t Bs[2][BN][KP];   // [n][k]

    const int t = threadIdx.x;
    const int bm = blockIdx.y * BM;
    const int bn = blockIdx.x * BN;
    const int warp = t >> 5, lane = t & 31;
    const int g = lane >> 2, t4 = lane & 3;
    const int wm = (warp / WCOLS) * WM, wn = (warp % WCOLS) * WN;

    // per-lane ldmatrix source addresses (A: m-rows; B: n-rows)
    const uint32_t aBase =
        (uint32_t)__cvta_generic_to_shared(&As[0][0][0]);
    const uint32_t bBase =
        (uint32_t)__cvta_generic_to_shared(&Bs[0][0][0]);
    const uint32_t aLane =
        aBase + (((wm + (lane & 15)) * AP + ((lane & 16) >> 2)) << 2);
    const uint32_t bLane =
        bBase +
        (((wn + (lane & 7) + ((lane & 16) >> 1)) * KP + ((lane & 8) >> 1))
         << 2);
    constexpr uint32_t AsBytes = BM * AP * 4;
    constexpr uint32_t BsBytes = BN * KP * 4;

    // gmem staging
    float4 pa[LA];
    float pbv[8];
    const int bn_n = t & (BN - 1);            // n within tile
    const int bkb = (t / BN) * 8;             // k base (0 or 8)

    auto ldg = [&](int k0) {
#pragma unroll
        for (int r = 0; r < LA; r++) {
            int id = t + 256 * r;
            int row = id >> 2, col = (id & 3) * 4;
            int gr = bm + row;
            pa[r] = (gr < M) ? *(const float4*)(A + (size_t)gr * K + k0 + col)
                             : make_float4(0.f, 0.f, 0.f, 0.f);
        }
#pragma unroll
        for (int c = 0; c < 8; c++)
            pbv[c] = B[(size_t)(k0 + bkb + c) * N + bn + bn_n];
    };
    auto sts = [&](int s) {
#pragma unroll
        for (int r = 0; r < LA; r++) {
            int id = t + 256 * r;
            int row = id >> 2, col = (id & 3) * 4;
            uint4 u;
            u.x = f2tf32(pa[r].x); u.y = f2tf32(pa[r].y);
            u.z = f2tf32(pa[r].z); u.w = f2tf32(pa[r].w);
            *(uint4*)&As[s][row][col] = u;
        }
        uint4 u0, u1;
        u0.x = f2tf32(pbv[0]); u0.y = f2tf32(pbv[1]);
        u0.z = f2tf32(pbv[2]); u0.w = f2tf32(pbv[3]);
        u1.x = f2tf32(pbv[4]); u1.y = f2tf32(pbv[5]);
        u1.z = f2tf32(pbv[6]); u1.w = f2tf32(pbv[7]);
        *(uint4*)&Bs[s][bn_n][bkb] = u0;
        *(uint4*)&Bs[s][bn_n][bkb + 4] = u1;
    };

    float acc[MI][NJ][4];
#pragma unroll
    for (int i = 0; i < MI; i++)
#pragma unroll
        for (int j = 0; j < NJ; j++)
#pragma unroll
            for (int r = 0; r < 4; r++) acc[i][j][r] = 0.f;

    const int nIter = K / GBK;
    ldg(0);
    sts(0);
    __syncthreads();

    for (int it = 0; it < nIter; it++) {
        const int s = it & 1;
        if (it + 1 < nIter) ldg((it + 1) * GBK);
        const uint32_t aBuf = aLane + s * AsBytes;
        const uint32_t bBuf = bLane + s * BsBytes;
#pragma unroll
        for (int kk = 0; kk < 2; kk++) {
            uint32_t af[MI][4], bf[NJ][2];
#pragma unroll
            for (int i = 0; i < MI; i++)
                ldsm_x4(af[i][0], af[i][1], af[i][2], af[i][3],
                        aBuf + kk * 32 + i * (16 * AP * 4));
#pragma unroll
            for (int j2 = 0; j2 < NJ / 2; j2++)
                ldsm_x4(bf[2 * j2][0], bf[2 * j2][1], bf[2 * j2 + 1][0],
                        bf[2 * j2 + 1][1],
                        bBuf + kk * 32 + j2 * (16 * KP * 4));
#pragma unroll
            for (int i = 0; i < MI; i++)
#pragma unroll
                for (int j = 0; j < NJ; j++) mma_tf32(acc[i][j], af[i], bf[j]);
        }
        if (it + 1 < nIter) {
            sts(s ^ 1);
            __syncthreads();
        }
    }

    // epilogue: half store + fused partial dots into as/ad via atomics
#pragma unroll
    for (int i = 0; i < MI; i++) {
        int r0 = bm + wm + i * 16 + g;
        int r1 = r0 + 8;
        float s0 = 0.f, d0 = 0.f, s1 = 0.f, d1 = 0.f;
#pragma unroll
        for (int j = 0; j < NJ; j++) {
            int c = bn + wn + j * 8 + 2 * t4;
            float a0 = av[c], a1 = av[c + 1];
            float e0 = dv[c], e1 = dv[c + 1];
            s0 += acc[i][j][0] * a0 + acc[i][j][1] * a1;
            d0 += acc[i][j][0] * e0 + acc[i][j][1] * e1;
            s1 += acc[i][j][2] * a0 + acc[i][j][3] * a1;
            d1 += acc[i][j][2] * e0 + acc[i][j][3] * e1;
            if (r0 < M)
                *(__half2*)(Ch + (size_t)r0 * N + c) =
                    __floats2half2_rn(acc[i][j][0], acc[i][j][1]);
            if (r1 < M)
                *(__half2*)(Ch + (size_t)r1 * N + c) =
                    __floats2half2_rn(acc[i][j][2], acc[i][j][3]);
        }
#pragma unroll
        for (int o = 1; o < 4; o <<= 1) {
            s0 += __shfl_xor_sync(~0u, s0, o);
            d0 += __shfl_xor_sync(~0u, d0, o);
            s1 += __shfl_xor_sync(~0u, s1, o);
            d1 += __shfl_xor_sync(~0u, d1, o);
        }
        if (t4 == 0) {
            if (r0 < M) {
                atomicAdd(&as_out[r0], s0);
                atomicAdd(&ad_out[r0], d0);
            }
            if (r1 < M) {
                atomicAdd(&as_out[r1], s1);
                atomicAdd(&ad_out[r1], d1);
            }
        }
    }
}

__device__ __forceinline__ float leaky(float x) {
    return fmaxf(x, NEG_SLOPE * x);
}

// -------- warp-per-node fused alpha + softmax + fp16 gather aggregation ----
template <int C, bool RELU>
__global__ void aggregate_kernel(const __half* __restrict__ hh,
                                 const float* __restrict__ bias,
                                 float* __restrict__ out,
                                 const float* __restrict__ asv,
                                 const float* __restrict__ adv,
                                 const float* __restrict__ aev, int N,
                                 int layer) {
    int warp = (blockIdx.x * blockDim.x + threadIdx.x) >> 5;
    int lane = threadIdx.x & 31;
    if (warp >= N) return;
    const int n = warp;
    const int rs = d_row[n], re = d_row[n + 1];
    const float adn = adv[n];
    float eself = __expf(leaky(asv[n] + adn + d_loopae[layer]));
    // pass 1: per-edge exp(leaky(logit)), lane-parallel; logits are O(1)
    float ssum = 0.f;
    for (int j = rs + lane; j < re; j += 32) {
        int s = d_csr_src[j];
        float ex = __expf(leaky(asv[s] + aev[j] + adn));
        d_alpha[j] = ex;
        ssum += ex;
    }
    for (int o = 16; o; o >>= 1) ssum += __shfl_xor_sync(~0u, ssum, o);
    __syncwarp();  // fence d_alpha stores before cross-lane reads
    float inv = 1.f / (ssum + eself);

    constexpr int NH2 = C / 64;  // half2 per lane (4 for C=256, 2 for C=128)
    float acc[2 * NH2];
    union U4 { uint4 v; __half2 h2[4]; };
    union U2 { uint2 v; __half2 h2[2]; };

    auto accum = [&](int s, float w) {
        if constexpr (C == 256) {
            U4 r; r.v = ((const uint4*)(hh + (size_t)s * C))[lane];
#pragma unroll
            for (int k = 0; k < 4; k++) {
                float2 f = __half22float2(r.h2[k]);
                acc[2 * k] += w * f.x;
                acc[2 * k + 1] += w * f.y;
            }
        } else {
            U2 r; r.v = ((const uint2*)(hh + (size_t)s * C))[lane];
#pragma unroll
            for (int k = 0; k < 2; k++) {
                float2 f = __half22float2(r.h2[k]);
                acc[2 * k] += w * f.x;
                acc[2 * k + 1] += w * f.y;
            }
        }
    };

#pragma unroll
    for (int k = 0; k < 2 * NH2; k++) acc[k] = 0.f;
    accum(n, eself * inv);  // self loop

    // 4x unrolled edge loop -> gather MLP=4
    int j = rs;
    for (; j + 4 <= re; j += 4) {
        float w0 = d_alpha[j] * inv, w1 = d_alpha[j + 1] * inv;
        float w2 = d_alpha[j + 2] * inv, w3 = d_alpha[j + 3] * inv;
        int s0 = d_csr_src[j], s1 = d_csr_src[j + 1];
        int s2 = d_csr_src[j + 2], s3 = d_csr_src[j + 3];
        if constexpr (C == 256) {
            U4 r0, r1, r2, r3;
            r0.v = ((const uint4*)(hh + (size_t)s0 * C))[lane];
            r1.v = ((const uint4*)(hh + (size_t)s1 * C))[lane];
            r2.v = ((const uint4*)(hh + (size_t)s2 * C))[lane];
            r3.v = ((const uint4*)(hh + (size_t)s3 * C))[lane];
#pragma unroll
            for (int k = 0; k < 4; k++) {
                float2 f0 = __half22float2(r0.h2[k]);
                float2 f1 = __half22float2(r1.h2[k]);
                float2 f2 = __half22float2(r2.h2[k]);
                float2 f3 = __half22float2(r3.h2[k]);
                acc[2 * k] += w0 * f0.x + w1 * f1.x + w2 * f2.x + w3 * f3.x;
                acc[2 * k + 1] +=
                    w0 * f0.y + w1 * f1.y + w2 * f2.y + w3 * f3.y;
            }
        } else {
            U2 r0, r1, r2, r3;
            r0.v = ((const uint2*)(hh + (size_t)s0 * C))[lane];
            r1.v = ((const uint2*)(hh + (size_t)s1 * C))[lane];
            r2.v = ((const uint2*)(hh + (size_t)s2 * C))[lane];
            r3.v = ((const uint2*)(hh + (size_t)s3 * C))[lane];
#pragma unroll
            for (int k = 0; k < 2; k++) {
                float2 f0 = __half22float2(r0.h2[k]);
                float2 f1 = __half22float2(r1.h2[k]);
                float2 f2 = __half22float2(r2.h2[k]);
                float2 f3 = __half22float2(r3.h2[k]);
                acc[2 * k] += w0 * f0.x + w1 * f1.x + w2 * f2.x + w3 * f3.x;
                acc[2 * k + 1] +=
                    w0 * f0.y + w1 * f1.y + w2 * f2.y + w3 * f3.y;
            }
        }
    }
    for (; j < re; j++) accum(d_csr_src[j], d_alpha[j] * inv);

    // write out: lane owns columns [lane*2*NH2, +2*NH2)
    const int base = lane * 2 * NH2;
    float* op = out + (size_t)n * C + base;
    const float* bp = bias + base;
#pragma unroll
    for (int k = 0; k < 2 * NH2; k += 4) {
        float4 b = *(const float4*)(bp + k);
        float4 o = make_float4(acc[k] + b.x, acc[k + 1] + b.y,
                               acc[k + 2] + b.z, acc[k + 3] + b.w);
        if (RELU) {
            o.x = fmaxf(o.x, 0.f);
            o.y = fmaxf(o.y, 0.f);
            o.z = fmaxf(o.z, 0.f);
            o.w = fmaxf(o.w, 0.f);
        }
        *(float4*)(op + k) = o;
    }
}

// ---------------- launch ----------------------------------------------------
extern "C" void kernel_launch(void* const* d_in, const int* in_sizes, int n_in,
                              void* d_out, int out_size) {
    const float* x   = (const float*)d_in[0];
    const int*   ei  = (const int*)d_in[1];
    const float* ea  = (const float*)d_in[2];
    const float* W1  = (const float*)d_in[3];
    const float* We1 = (const float*)d_in[4];
    const float* as1 = (const float*)d_in[5];
    const float* ad1 = (const float*)d_in[6];
    const float* ae1 = (const float*)d_in[7];
    const float* b1  = (const float*)d_in[8];
    const float* W2  = (const float*)d_in[9];
    const float* We2 = (const float*)d_in[10];
    const float* as2 = (const float*)d_in[11];
    const float* ad2 = (const float*)d_in[12];
    const float* ae2 = (const float*)d_in[13];
    const float* b2  = (const float*)d_in[14];
    float* out = (float*)d_out;

    const int E = in_sizes[2] / ED;
    const int N = in_sizes[0] / CIN;
    const int* srcp = ei;
    const int* dstp = ei + E;

    void* p;
    cudaGetSymbolAddress(&p, d_hh);     __half* hhp   = (__half*)p;
    cudaGetSymbolAddress(&p, d_hidden); float* hidbuf = (float*)p;
    cudaGetSymbolAddress(&p, d_aev1);   float* aev1p  = (float*)p;
    cudaGetSymbolAddress(&p, d_aev2);   float* aev2p  = (float*)p;
    cudaGetSymbolAddress(&p, d_as1);    float* as1p   = (float*)p;
    cudaGetSymbolAddress(&p, d_ad1);    float* ad1p   = (float*)p;
    cudaGetSymbolAddress(&p, d_as2);    float* as2p   = (float*)p;
    cudaGetSymbolAddress(&p, d_ad2);    float* ad2p   = (float*)p;

    const int TPB = 256;
    const int warpsPerBlock = TPB / 32;
    const int nodeBlocks = (N + warpsPerBlock - 1) / warpsPerBlock;

    // 1-3: structure build prologue (zero_v NEEDS 512 threads: 16 warps for v)
    zero_v_kernel<<<128, 512>>>(We1, ae1, We2, ae2, N);
    hist_kernel<<<512, TPB>>>(dstp, ea, E);           // grid-stride (R6 lesson)
    scan_kernel<<<1, 1024>>>(N, 1.f / (float)E);

    // 4: layer-1 GEMM (+fused dots, half output) — 4th launch for ncu
    {
        dim3 g(CHID / 128, (N + 127) / 128);
        mma_gemm_kernel<128, 128, 64, 32><<<g, 256>>>(
            x, W1, hhp, as1, ad1, as1p, ad1p, N, CHID, CIN);
    }
    // 5: CSR scatter (independent of GEMM)
    scatter_kernel<<<512, TPB>>>(srcp, dstp, E);      // grid-stride (R6 lesson)

    // 6: layer-1 fused alpha+softmax+aggregate (fp16 gather)
    aggregate_kernel<CHID, true><<<nodeBlocks, TPB>>>(hhp, b1, hidbuf, as1p,
                                                      ad1p, aev1p, N, 0);

    // 7: layer-2 GEMM (+fused dots, half output)
    {
        dim3 g(COUT / 128, (N + 63) / 64);
        mma_gemm_kernel<64, 128, 32, 32><<<g, 256>>>(
            hidbuf, W2, hhp, as2, ad2, as2p, ad2p, N, COUT, CHID);
    }
    // 8: layer-2 fused aggregate
    aggregate_kernel<COUT, false><<<nodeBlocks, TPB>>>(hhp, b2, out, as2p,
                                                       ad2p, aev2p, N, 1);
}

// round 8
// speedup vs baseline: 1.4833x; 1.0062x over previous
#include <cuda_runtime.h>
#include <cuda_fp16.h>
#include <cstdint>

#define NEG_SLOPE 0.2f

static constexpr int MAXN = 50000;
static constexpr int MAXE = 800000;
static constexpr int CIN  = 128;
static constexpr int CHID = 256;
static constexpr int COUT = 128;
static constexpr int ED   = 8;

// ---------------- scratch (static device globals; no allocation allowed) ---
__device__ int    d_deg[MAXN];
__device__ int    d_row[MAXN + 1];
__device__ int    d_cur[MAXN];
__device__ int    d_csr_src[MAXE];
__device__ float  d_tmpa[MAXE];   // edge-ordered aev1
__device__ float  d_tmpb[MAXE];   // edge-ordered aev2
__device__ float  d_aev1[MAXE];   // CSR-ordered
__device__ float  d_aev2[MAXE];
__device__ float  d_alpha[MAXE];  // exp(leaky(logit)) per CSR edge
__device__ __half d_hh[(size_t)MAXN * CHID];   // transformed feats (fp16)
__device__ __half d_hid[(size_t)MAXN * CHID];  // relu(layer1 out) (fp16)
__device__ float  d_as1[MAXN];
__device__ float  d_ad1[MAXN];
__device__ float  d_as2[MAXN];
__device__ float  d_ad2[MAXN];
__device__ float  d_easum[ED];
__device__ float  d_v[2][ED];
__device__ float  d_loopae[2];

// ---------------- zero + compute v (MUST run with >=512 threads/block) -----
__global__ void zero_v_kernel(const float* __restrict__ We1,
                              const float* __restrict__ ae1,
                              const float* __restrict__ We2,
                              const float* __restrict__ ae2, int n) {
    for (int i = blockIdx.x * blockDim.x + threadIdx.x; i < n;
         i += gridDim.x * blockDim.x) {
        d_deg[i] = 0;
        d_as1[i] = 0.f; d_ad1[i] = 0.f;
        d_as2[i] = 0.f; d_ad2[i] = 0.f;
    }
    if (blockIdx.x == 0) {
        if (threadIdx.x < ED) d_easum[threadIdx.x] = 0.f;
        int wid = threadIdx.x >> 5, lane = threadIdx.x & 31;
        if (wid < ED) {
            float s = 0.f;
            for (int c = lane; c < CHID; c += 32) s += We1[wid * CHID + c] * ae1[c];
            for (int o = 16; o; o >>= 1) s += __shfl_xor_sync(~0u, s, o);
            if (!lane) d_v[0][wid] = s;
        } else if (wid < 2 * ED) {
            int r = wid - ED;
            float s = 0.f;
            for (int c = lane; c < COUT; c += 32) s += We2[r * COUT + c] * ae2[c];
            for (int o = 16; o; o >>= 1) s += __shfl_xor_sync(~0u, s, o);
            if (!lane) d_v[1][r] = s;
        }
    }
}

// histogram of dst degrees + easum + per-edge attr attention (grid-stride)
__global__ void hist_kernel(const int* __restrict__ dstp,
                            const float* __restrict__ ea, int E) {
    __shared__ float ss[ED];
    if (threadIdx.x < ED) ss[threadIdx.x] = 0.f;
    __syncthreads();
    float v1[ED], v2[ED];
#pragma unroll
    for (int k = 0; k < ED; k++) { v1[k] = d_v[0][k]; v2[k] = d_v[1][k]; }
    float ls[ED] = {};
    for (int i = blockIdx.x * blockDim.x + threadIdx.x; i < E;
         i += gridDim.x * blockDim.x) {
        atomicAdd(&d_deg[dstp[i]], 1);
        const float4* p = (const float4*)(ea + (size_t)i * ED);
        float4 a = p[0], b = p[1];
        ls[0] += a.x; ls[1] += a.y; ls[2] += a.z; ls[3] += a.w;
        ls[4] += b.x; ls[5] += b.y; ls[6] += b.z; ls[7] += b.w;
        d_tmpa[i] = a.x * v1[0] + a.y * v1[1] + a.z * v1[2] + a.w * v1[3] +
                    b.x * v1[4] + b.y * v1[5] + b.z * v1[6] + b.w * v1[7];
        d_tmpb[i] = a.x * v2[0] + a.y * v2[1] + a.z * v2[2] + a.w * v2[3] +
                    b.x * v2[4] + b.y * v2[5] + b.z * v2[6] + b.w * v2[7];
    }
#pragma unroll
    for (int k = 0; k < ED; k++) atomicAdd(&ss[k], ls[k]);
    __syncthreads();
    if (threadIdx.x < ED) atomicAdd(&d_easum[threadIdx.x], ss[threadIdx.x]);
}

// single-block exclusive scan of d_deg -> d_row / d_cur ; + loopae
__global__ void scan_kernel(int n, float Einv) {
    __shared__ int partial[1024];
    const int t = threadIdx.x;
    const int CHK = (n + 1023) / 1024;
    int start = t * CHK;
    int end = start + CHK; if (end > n) end = n;
    int s = 0;
    for (int i = start; i < end; i++) s += d_deg[i];
    partial[t] = s;
    __syncthreads();
    for (int off = 1; off < 1024; off <<= 1) {
        int v = (t >= off) ? partial[t - off] : 0;
        __syncthreads();
        partial[t] += v;
        __syncthreads();
    }
    int run = (t == 0) ? 0 : partial[t - 1];
    for (int i = start; i < end; i++) {
        d_row[i] = run;
        d_cur[i] = run;
        run += d_deg[i];
    }
    if (t == 1023) d_row[n] = partial[1023];
    if (t < 2) {
        float la = 0.f;
#pragma unroll
        for (int i = 0; i < ED; i++) la += d_easum[i] * Einv * d_v[t][i];
        d_loopae[t] = la;
    }
}

// scatter edges into CSR-by-dst; permute precomputed aev (grid-stride)
__global__ void scatter_kernel(const int* __restrict__ srcp,
                               const int* __restrict__ dstp, int E) {
    for (int e = blockIdx.x * blockDim.x + threadIdx.x; e < E;
         e += gridDim.x * blockDim.x) {
        int d = dstp[e];
        int pos = atomicAdd(&d_cur[d], 1);
        d_csr_src[pos] = srcp[e];
        d_aev1[pos] = d_tmpa[e];
        d_aev2[pos] = d_tmpb[e];
    }
}

// ---------------- fp16 tensor-core GEMM (m16n8k16, fp32 acc) ---------------
__device__ __forceinline__ void mma_f16(float* d, const uint32_t* a,
                                        const uint32_t* b) {
    asm volatile(
        "mma.sync.aligned.m16n8k16.row.col.f32.f16.f16.f32 "
        "{%0,%1,%2,%3}, {%4,%5,%6,%7}, {%8,%9}, {%0,%1,%2,%3};\n"
        : "+f"(d[0]), "+f"(d[1]), "+f"(d[2]), "+f"(d[3])
        : "r"(a[0]), "r"(a[1]), "r"(a[2]), "r"(a[3]), "r"(b[0]), "r"(b[1]));
}
__device__ __forceinline__ void ldsm_x4(uint32_t& r0, uint32_t& r1,
                                        uint32_t& r2, uint32_t& r3,
                                        uint32_t addr) {
    asm volatile(
        "ldmatrix.sync.aligned.m8n8.x4.shared.b16 {%0,%1,%2,%3}, [%4];"
        : "=r"(r0), "=r"(r1), "=r"(r2), "=r"(r3)
        : "r"(addr));
}
__device__ __forceinline__ uint32_t pack_h2(float x, float y) {
    __half2 h = __floats2half2_rn(x, y);
    return *(uint32_t*)&h;
}

// Ch[M,N] = half(A[M,K] @ B[K,N]); fused fp32 dots:
// as_out[m] += sum_c C[m,c]*av[c], ad_out[m] += sum_c C[m,c]*dv[c]
// Fixed: BM=64, BN=128, WM=32, WN=32, 256 threads (8 warps 2x4)
template <typename TA>
__global__ __launch_bounds__(256, 3) void mma_gemm_kernel(
    const TA* __restrict__ A, const float* __restrict__ B,
    __half* __restrict__ Ch, const float* __restrict__ av,
    const float* __restrict__ dv, float* __restrict__ as_out,
    float* __restrict__ ad_out, int M, int N, int K) {
    constexpr int BM = 64, BN = 128, WM = 32, WN = 32;
    constexpr int GBK = 16;
    constexpr int RP = 24;  // halves per smem row (16 data + 8 pad) = 48B
    constexpr int WCOLS = BN / WN;  // 4
    constexpr int MI = WM / 16;     // 2
    constexpr int NJ = WN / 8;      // 4

    __shared__ __align__(16) __half As[2][BM][RP];
    __shared__ __align__(16) __half Bs[2][BN][RP];

    const int t = threadIdx.x;
    const int bm = blockIdx.y * BM;
    const int bn = blockIdx.x * BN;
    const int warp = t >> 5, lane = t & 31;
    const int g = lane >> 2, t4 = lane & 3;
    const int wm = (warp / WCOLS) * WM, wn = (warp % WCOLS) * WN;

    // ldmatrix lane addresses
    const uint32_t aBase = (uint32_t)__cvta_generic_to_shared(&As[0][0][0]);
    const uint32_t bBase = (uint32_t)__cvta_generic_to_shared(&Bs[0][0][0]);
    // A: matrices [m0-7/k0-7, m8-15/k0-7, m0-7/k8-15, m8-15/k8-15]
    const uint32_t aLane = aBase + (wm + (lane & 15)) * 48 + (lane & 16);
    // B (n-major): matrices [n0-7/k0-7, n0-7/k8-15, n8-15/k0-7, n8-15/k8-15]
    const uint32_t bLane =
        bBase + (wn + (lane & 7) + ((lane & 16) >> 1)) * 48 + ((lane & 8) << 1);
    constexpr uint32_t AsBytes = BM * RP * 2;
    constexpr uint32_t BsBytes = BN * RP * 2;

    // gmem staging: A = 4 elems/thread (row t>>2, cols (t&3)*4)
    // B = 8 k-elems/thread (n = t&127, kchunk (t>>7)*8)
    const int arow = t >> 2, acol = (t & 3) * 4;
    const int bn_n = t & (BN - 1), bkb = (t / BN) * 8;

    float4 paf;     // TA=float staging
    uint2 pah;      // TA=half staging
    float pbv[8];

    auto ldg = [&](int k0) {
        int gr = bm + arow;
        if constexpr (sizeof(TA) == 4) {
            paf = (gr < M)
                      ? *(const float4*)((const float*)A + (size_t)gr * K + k0 + acol)
                      : make_float4(0.f, 0.f, 0.f, 0.f);
        } else {
            pah = (gr < M)
                      ? *(const uint2*)((const __half*)A + (size_t)gr * K + k0 + acol)
                      : make_uint2(0u, 0u);
        }
#pragma unroll
        for (int c = 0; c < 8; c++)
            pbv[c] = B[(size_t)(k0 + bkb + c) * N + bn + bn_n];
    };
    auto sts = [&](int s) {
        if constexpr (sizeof(TA) == 4) {
            uint2 u;
            u.x = pack_h2(paf.x, paf.y);
            u.y = pack_h2(paf.z, paf.w);
            *(uint2*)&As[s][arow][acol] = u;
        } else {
            *(uint2*)&As[s][arow][acol] = pah;
        }
        uint4 u;
        u.x = pack_h2(pbv[0], pbv[1]);
        u.y = pack_h2(pbv[2], pbv[3]);
        u.z = pack_h2(pbv[4], pbv[5]);
        u.w = pack_h2(pbv[6], pbv[7]);
        *(uint4*)&Bs[s][bn_n][bkb] = u;
    };

    float acc[MI][NJ][4];
#pragma unroll
    for (int i = 0; i < MI; i++)
#pragma unroll
        for (int j = 0; j < NJ; j++)
#pragma unroll
            for (int r = 0; r < 4; r++) acc[i][j][r] = 0.f;

    const int nIter = K / GBK;
    ldg(0);
    sts(0);
    __syncthreads();

    for (int it = 0; it < nIter; it++) {
        const int s = it & 1;
        if (it + 1 < nIter) ldg((it + 1) * GBK);
        const uint32_t aBuf = aLane + s * AsBytes;
        const uint32_t bBuf = bLane + s * BsBytes;
        uint32_t af[MI][4], bf[NJ][2];
#pragma unroll
        for (int i = 0; i < MI; i++)
            ldsm_x4(af[i][0], af[i][1], af[i][2], af[i][3], aBuf + i * 16 * 48);
#pragma unroll
        for (int j2 = 0; j2 < NJ / 2; j2++)
            ldsm_x4(bf[2 * j2][0], bf[2 * j2][1], bf[2 * j2 + 1][0],
                    bf[2 * j2 + 1][1], bBuf + j2 * 16 * 48);
#pragma unroll
        for (int i = 0; i < MI; i++)
#pragma unroll
            for (int j = 0; j < NJ; j++) mma_f16(acc[i][j], af[i], bf[j]);
        if (it + 1 < nIter) {
            sts(s ^ 1);
            __syncthreads();
        }
    }

    // epilogue: half store + fused partial dots into as/ad via atomics
#pragma unroll
    for (int i = 0; i < MI; i++) {
        int r0 = bm + wm + i * 16 + g;
        int r1 = r0 + 8;
        float s0 = 0.f, d0 = 0.f, s1 = 0.f, d1 = 0.f;
#pragma unroll
        for (int j = 0; j < NJ; j++) {
            int c = bn + wn + j * 8 + 2 * t4;
            float a0 = av[c], a1 = av[c + 1];
            float e0 = dv[c], e1 = dv[c + 1];
            s0 += acc[i][j][0] * a0 + acc[i][j][1] * a1;
            d0 += acc[i][j][0] * e0 + acc[i][j][1] * e1;
            s1 += acc[i][j][2] * a0 + acc[i][j][3] * a1;
            d1 += acc[i][j][2] * e0 + acc[i][j][3] * e1;
            if (r0 < M)
                *(__half2*)(Ch + (size_t)r0 * N + c) =
                    __floats2half2_rn(acc[i][j][0], acc[i][j][1]);
            if (r1 < M)
                *(__half2*)(Ch + (size_t)r1 * N + c) =
                    __floats2half2_rn(acc[i][j][2], acc[i][j][3]);
        }
#pragma unroll
        for (int o = 1; o < 4; o <<= 1) {
            s0 += __shfl_xor_sync(~0u, s0, o);
            d0 += __shfl_xor_sync(~0u, d0, o);
            s1 += __shfl_xor_sync(~0u, s1, o);
            d1 += __shfl_xor_sync(~0u, d1, o);
        }
        if (t4 == 0) {
            if (r0 < M) {
                atomicAdd(&as_out[r0], s0);
                atomicAdd(&ad_out[r0], d0);
            }
            if (r1 < M) {
                atomicAdd(&as_out[r1], s1);
                atomicAdd(&ad_out[r1], d1);
            }
        }
    }
}

__device__ __forceinline__ float leaky(float x) {
    return fmaxf(x, NEG_SLOPE * x);
}

// -------- warp-per-node fused alpha + softmax + fp16 gather aggregation ----
template <int C, bool RELU, typename TOUT>
__global__ void aggregate_kernel(const __half* __restrict__ hh,
                                 const float* __restrict__ bias,
                                 TOUT* __restrict__ out,
                                 const float* __restrict__ asv,
                                 const float* __restrict__ adv,
                                 const float* __restrict__ aev, int N,
                                 int layer) {
    int warp = (blockIdx.x * blockDim.x + threadIdx.x) >> 5;
    int lane = threadIdx.x & 31;
    if (warp >= N) return;
    const int n = warp;
    const int rs = d_row[n], re = d_row[n + 1];
    const float adn = adv[n];
    float eself = __expf(leaky(asv[n] + adn + d_loopae[layer]));
    // pass 1: per-edge exp(leaky(logit)), lane-parallel; logits are O(1)
    float ssum = 0.f;
    for (int j = rs + lane; j < re; j += 32) {
        int s = d_csr_src[j];
        float ex = __expf(leaky(asv[s] + aev[j] + adn));
        d_alpha[j] = ex;
        ssum += ex;
    }
    for (int o = 16; o; o >>= 1) ssum += __shfl_xor_sync(~0u, ssum, o);
    __syncwarp();  // fence d_alpha stores before cross-lane reads
    float inv = 1.f / (ssum + eself);

    constexpr int NH2 = C / 64;  // half2 per lane (4 for C=256, 2 for C=128)
    float acc[2 * NH2];
    union U4 { uint4 v; __half2 h2[4]; };
    union U2 { uint2 v; __half2 h2[2]; };

    auto accum = [&](int s, float w) {
        if constexpr (C == 256) {
            U4 r; r.v = ((const uint4*)(hh + (size_t)s * C))[lane];
#pragma unroll
            for (int k = 0; k < 4; k++) {
                float2 f = __half22float2(r.h2[k]);
                acc[2 * k] += w * f.x;
                acc[2 * k + 1] += w * f.y;
            }
        } else {
            U2 r; r.v = ((const uint2*)(hh + (size_t)s * C))[lane];
#pragma unroll
            for (int k = 0; k < 2; k++) {
                float2 f = __half22float2(r.h2[k]);
                acc[2 * k] += w * f.x;
                acc[2 * k + 1] += w * f.y;
            }
        }
    };

#pragma unroll
    for (int k = 0; k < 2 * NH2; k++) acc[k] = 0.f;
    accum(n, eself * inv);  // self loop

    // 4x unrolled edge loop -> gather MLP=4
    int j = rs;
    for (; j + 4 <= re; j += 4) {
        float w0 = d_alpha[j] * inv, w1 = d_alpha[j + 1] * inv;
        float w2 = d_alpha[j + 2] * inv, w3 = d_alpha[j + 3] * inv;
        int s0 = d_csr_src[j], s1 = d_csr_src[j + 1];
        int s2 = d_csr_src[j + 2], s3 = d_csr_src[j + 3];
        if constexpr (C == 256) {
            U4 r0, r1, r2, r3;
            r0.v = ((const uint4*)(hh + (size_t)s0 * C))[lane];
            r1.v = ((const uint4*)(hh + (size_t)s1 * C))[lane];
            r2.v = ((const uint4*)(hh + (size_t)s2 * C))[lane];
            r3.v = ((const uint4*)(hh + (size_t)s3 * C))[lane];
#pragma unroll
            for (int k = 0; k < 4; k++) {
                float2 f0 = __half22float2(r0.h2[k]);
                float2 f1 = __half22float2(r1.h2[k]);
                float2 f2 = __half22float2(r2.h2[k]);
                float2 f3 = __half22float2(r3.h2[k]);
                acc[2 * k] += w0 * f0.x + w1 * f1.x + w2 * f2.x + w3 * f3.x;
                acc[2 * k + 1] +=
                    w0 * f0.y + w1 * f1.y + w2 * f2.y + w3 * f3.y;
            }
        } else {
            U2 r0, r1, r2, r3;
            r0.v = ((const uint2*)(hh + (size_t)s0 * C))[lane];
            r1.v = ((const uint2*)(hh + (size_t)s1 * C))[lane];
            r2.v = ((const uint2*)(hh + (size_t)s2 * C))[lane];
            r3.v = ((const uint2*)(hh + (size_t)s3 * C))[lane];
#pragma unroll
            for (int k = 0; k < 2; k++) {
                float2 f0 = __half22float2(r0.h2[k]);
                float2 f1 = __half22float2(r1.h2[k]);
                float2 f2 = __half22float2(r2.h2[k]);
                float2 f3 = __half22float2(r3.h2[k]);
                acc[2 * k] += w0 * f0.x + w1 * f1.x + w2 * f2.x + w3 * f3.x;
                acc[2 * k + 1] +=
                    w0 * f0.y + w1 * f1.y + w2 * f2.y + w3 * f3.y;
            }
        }
    }
    for (; j < re; j++) accum(d_csr_src[j], d_alpha[j] * inv);

    // write out: lane owns columns [lane*2*NH2, +2*NH2)
    const int base = lane * 2 * NH2;
    const float* bp = bias + base;
    float vv[2 * NH2];
#pragma unroll
    for (int k = 0; k < 2 * NH2; k++) {
        vv[k] = acc[k] + bp[k];
        if (RELU) vv[k] = fmaxf(vv[k], 0.f);
    }
    if constexpr (sizeof(TOUT) == 2) {
        __half2* op = (__half2*)((__half*)out + (size_t)n * C + base);
#pragma unroll
        for (int k = 0; k < NH2; k++)
            op[k] = __floats2half2_rn(vv[2 * k], vv[2 * k + 1]);
    } else {
        float* op = (float*)out + (size_t)n * C + base;
#pragma unroll
        for (int k = 0; k < 2 * NH2; k += 4)
            *(float4*)(op + k) =
                make_float4(vv[k], vv[k + 1], vv[k + 2], vv[k + 3]);
    }
}

// ---------------- launch ----------------------------------------------------
extern "C" void kernel_launch(void* const* d_in, const int* in_sizes, int n_in,
                              void* d_out, int out_size) {
    const float* x   = (const float*)d_in[0];
    const int*   ei  = (const int*)d_in[1];
    const float* ea  = (const float*)d_in[2];
    const float* W1  = (const float*)d_in[3];
    const float* We1 = (const float*)d_in[4];
    const float* as1 = (const float*)d_in[5];
    const float* ad1 = (const float*)d_in[6];
    const float* ae1 = (const float*)d_in[7];
    const float* b1  = (const float*)d_in[8];
    const float* W2  = (const float*)d_in[9];
    const float* We2 = (const float*)d_in[10];
    const float* as2 = (const float*)d_in[11];
    const float* ad2 = (const float*)d_in[12];
    const float* ae2 = (const float*)d_in[13];
    const float* b2  = (const float*)d_in[14];
    float* out = (float*)d_out;

    const int E = in_sizes[2] / ED;
    const int N = in_sizes[0] / CIN;
    const int* srcp = ei;
    const int* dstp = ei + E;

    void* p;
    cudaGetSymbolAddress(&p, d_hh);   __half* hhp  = (__half*)p;
    cudaGetSymbolAddress(&p, d_hid);  __half* hidp = (__half*)p;
    cudaGetSymbolAddress(&p, d_aev1); float* aev1p = (float*)p;
    cudaGetSymbolAddress(&p, d_aev2); float* aev2p = (float*)p;
    cudaGetSymbolAddress(&p, d_as1);  float* as1p  = (float*)p;
    cudaGetSymbolAddress(&p, d_ad1);  float* ad1p  = (float*)p;
    cudaGetSymbolAddress(&p, d_as2);  float* as2p  = (float*)p;
    cudaGetSymbolAddress(&p, d_ad2);  float* ad2p  = (float*)p;

    const int TPB = 256;
    const int warpsPerBlock = TPB / 32;
    const int nodeBlocks = (N + warpsPerBlock - 1) / warpsPerBlock;
    const int mBlocks = (N + 63) / 64;

    // 1-3: structure build prologue (zero_v NEEDS 512 threads: 16 warps for v)
    zero_v_kernel<<<128, 512>>>(We1, ae1, We2, ae2, N);
    hist_kernel<<<512, TPB>>>(dstp, ea, E);
    scan_kernel<<<1, 1024>>>(N, 1.f / (float)E);

    // 4: layer-1 GEMM (fp16 mma, +fused dots) — 4th launch for ncu
    mma_gemm_kernel<float><<<dim3(CHID / 128, mBlocks), 256>>>(
        x, W1, hhp, as1, ad1, as1p, ad1p, N, CHID, CIN);

    // 5: CSR scatter (independent of GEMM)
    scatter_kernel<<<512, TPB>>>(srcp, dstp, E);

    // 6: layer-1 fused alpha+softmax+aggregate -> fp16 hidden
    aggregate_kernel<CHID, true, __half><<<nodeBlocks, TPB>>>(
        hhp, b1, hidp, as1p, ad1p, aev1p, N, 0);

    // 7: layer-2 GEMM (fp16 A input, +fused dots)
    mma_gemm_kernel<__half><<<dim3(COUT / 128, mBlocks), 256>>>(
        hidp, W2, hhp, as2, ad2, as2p, ad2p, N, COUT, CHID);

    // 8: layer-2 fused aggregate -> fp32 output
    aggregate_kernel<COUT, false, float><<<nodeBlocks, TPB>>>(
        hhp, b2, out, as2p, ad2p, aev2p, N, 1);
}

// round 9
// speedup vs baseline: 1.5758x; 1.0624x over previous
#include <cuda_runtime.h>
#include <cuda_fp16.h>
#include <cstdint>

#define NEG_SLOPE 0.2f

static constexpr int MAXN = 50000;
static constexpr int MAXE = 800000;
static constexpr int CIN  = 128;
static constexpr int CHID = 256;
static constexpr int COUT = 128;
static constexpr int ED   = 8;

// ---------------- scratch (static device globals; no allocation allowed) ---
__device__ int    d_deg[MAXN];
__device__ int    d_row[MAXN + 1];
__device__ int    d_cur[MAXN];
__device__ int    d_csr_src[MAXE];
__device__ float  d_tmpa[MAXE];   // edge-ordered aev1
__device__ float  d_tmpb[MAXE];   // edge-ordered aev2
__device__ float  d_aev1[MAXE];   // CSR-ordered
__device__ float  d_aev2[MAXE];
__device__ float  d_alpha[MAXE];  // exp(leaky(logit)) per CSR edge
__device__ __half d_hh[(size_t)MAXN * CHID];   // transformed feats (fp16)
__device__ __half d_hid[(size_t)MAXN * CHID];  // relu(layer1 out) (fp16)
__device__ float  d_as1[MAXN];
__device__ float  d_ad1[MAXN];
__device__ float  d_as2[MAXN];
__device__ float  d_ad2[MAXN];
__device__ float  d_easum[ED];
__device__ float  d_v[2][ED];
__device__ float  d_loopae[2];

// ---------------- zero + compute v (MUST run with >=512 threads/block) -----
__global__ void zero_v_kernel(const float* __restrict__ We1,
                              const float* __restrict__ ae1,
                              const float* __restrict__ We2,
                              const float* __restrict__ ae2, int n) {
    for (int i = blockIdx.x * blockDim.x + threadIdx.x; i < n;
         i += gridDim.x * blockDim.x) {
        d_deg[i] = 0;
        d_as1[i] = 0.f; d_ad1[i] = 0.f;
        d_as2[i] = 0.f; d_ad2[i] = 0.f;
    }
    if (blockIdx.x == 0) {
        if (threadIdx.x < ED) d_easum[threadIdx.x] = 0.f;
        int wid = threadIdx.x >> 5, lane = threadIdx.x & 31;
        if (wid < ED) {
            float s = 0.f;
            for (int c = lane; c < CHID; c += 32) s += We1[wid * CHID + c] * ae1[c];
            for (int o = 16; o; o >>= 1) s += __shfl_xor_sync(~0u, s, o);
            if (!lane) d_v[0][wid] = s;
        } else if (wid < 2 * ED) {
            int r = wid - ED;
            float s = 0.f;
            for (int c = lane; c < COUT; c += 32) s += We2[r * COUT + c] * ae2[c];
            for (int o = 16; o; o >>= 1) s += __shfl_xor_sync(~0u, s, o);
            if (!lane) d_v[1][r] = s;
        }
    }
}

// histogram of dst degrees + easum + per-edge attr attention (grid-stride)
__global__ void hist_kernel(const int* __restrict__ dstp,
                            const float* __restrict__ ea, int E) {
    __shared__ float ss[ED];
    if (threadIdx.x < ED) ss[threadIdx.x] = 0.f;
    __syncthreads();
    float v1[ED], v2[ED];
#pragma unroll
    for (int k = 0; k < ED; k++) { v1[k] = d_v[0][k]; v2[k] = d_v[1][k]; }
    float ls[ED] = {};
    for (int i = blockIdx.x * blockDim.x + threadIdx.x; i < E;
         i += gridDim.x * blockDim.x) {
        atomicAdd(&d_deg[dstp[i]], 1);
        const float4* p = (const float4*)(ea + (size_t)i * ED);
        float4 a = p[0], b = p[1];
        ls[0] += a.x; ls[1] += a.y; ls[2] += a.z; ls[3] += a.w;
        ls[4] += b.x; ls[5] += b.y; ls[6] += b.z; ls[7] += b.w;
        d_tmpa[i] = a.x * v1[0] + a.y * v1[1] + a.z * v1[2] + a.w * v1[3] +
                    b.x * v1[4] + b.y * v1[5] + b.z * v1[6] + b.w * v1[7];
        d_tmpb[i] = a.x * v2[0] + a.y * v2[1] + a.z * v2[2] + a.w * v2[3] +
                    b.x * v2[4] + b.y * v2[5] + b.z * v2[6] + b.w * v2[7];
    }
#pragma unroll
    for (int k = 0; k < ED; k++) atomicAdd(&ss[k], ls[k]);
    __syncthreads();
    if (threadIdx.x < ED) atomicAdd(&d_easum[threadIdx.x], ss[threadIdx.x]);
}

// single-block exclusive scan of d_deg -> d_row / d_cur ; + loopae
__global__ void scan_kernel(int n, float Einv) {
    __shared__ int partial[1024];
    const int t = threadIdx.x;
    const int CHK = (n + 1023) / 1024;
    int start = t * CHK;
    int end = start + CHK; if (end > n) end = n;
    int s = 0;
    for (int i = start; i < end; i++) s += d_deg[i];
    partial[t] = s;
    __syncthreads();
    for (int off = 1; off < 1024; off <<= 1) {
        int v = (t >= off) ? partial[t - off] : 0;
        __syncthreads();
        partial[t] += v;
        __syncthreads();
    }
    int run = (t == 0) ? 0 : partial[t - 1];
    for (int i = start; i < end; i++) {
        d_row[i] = run;
        d_cur[i] = run;
        run += d_deg[i];
    }
    if (t == 1023) d_row[n] = partial[1023];
    if (t < 2) {
        float la = 0.f;
#pragma unroll
        for (int i = 0; i < ED; i++) la += d_easum[i] * Einv * d_v[t][i];
        d_loopae[t] = la;
    }
}

// scatter edges into CSR-by-dst; 4 strided edges per loop body -> atomic MLP=4
__global__ void scatter_kernel(const int* __restrict__ srcp,
                               const int* __restrict__ dstp, int E) {
    const int st = gridDim.x * blockDim.x;
    for (int e = blockIdx.x * blockDim.x + threadIdx.x; e < E; e += 4 * st) {
        int e1 = e + st, e2 = e + 2 * st, e3 = e + 3 * st;
        bool v1 = e1 < E, v2 = e2 < E, v3 = e3 < E;
        int d0 = dstp[e];
        int d1 = v1 ? dstp[e1] : 0;
        int d2 = v2 ? dstp[e2] : 0;
        int d3 = v3 ? dstp[e3] : 0;
        int p0 = atomicAdd(&d_cur[d0], 1);
        int p1 = v1 ? atomicAdd(&d_cur[d1], 1) : 0;
        int p2 = v2 ? atomicAdd(&d_cur[d2], 1) : 0;
        int p3 = v3 ? atomicAdd(&d_cur[d3], 1) : 0;
        d_csr_src[p0] = srcp[e];
        d_aev1[p0] = d_tmpa[e];
        d_aev2[p0] = d_tmpb[e];
        if (v1) { d_csr_src[p1] = srcp[e1]; d_aev1[p1] = d_tmpa[e1]; d_aev2[p1] = d_tmpb[e1]; }
        if (v2) { d_csr_src[p2] = srcp[e2]; d_aev1[p2] = d_tmpa[e2]; d_aev2[p2] = d_tmpb[e2]; }
        if (v3) { d_csr_src[p3] = srcp[e3]; d_aev1[p3] = d_tmpa[e3]; d_aev2[p3] = d_tmpb[e3]; }
    }
}

// ---------------- fp16 tensor-core GEMM (m16n8k16, fp32 acc) ---------------
__device__ __forceinline__ void mma_f16(float* d, const uint32_t* a,
                                        const uint32_t* b) {
    asm volatile(
        "mma.sync.aligned.m16n8k16.row.col.f32.f16.f16.f32 "
        "{%0,%1,%2,%3}, {%4,%5,%6,%7}, {%8,%9}, {%0,%1,%2,%3};\n"
        : "+f"(d[0]), "+f"(d[1]), "+f"(d[2]), "+f"(d[3])
        : "r"(a[0]), "r"(a[1]), "r"(a[2]), "r"(a[3]), "r"(b[0]), "r"(b[1]));
}
__device__ __forceinline__ void ldsm_x4(uint32_t& r0, uint32_t& r1,
                                        uint32_t& r2, uint32_t& r3,
                                        uint32_t addr) {
    asm volatile(
        "ldmatrix.sync.aligned.m8n8.x4.shared.b16 {%0,%1,%2,%3}, [%4];"
        : "=r"(r0), "=r"(r1), "=r"(r2), "=r"(r3)
        : "r"(addr));
}
__device__ __forceinline__ void ldsm_x4_trans(uint32_t& r0, uint32_t& r1,
                                              uint32_t& r2, uint32_t& r3,
                                              uint32_t addr) {
    asm volatile(
        "ldmatrix.sync.aligned.m8n8.x4.trans.shared.b16 {%0,%1,%2,%3}, [%4];"
        : "=r"(r0), "=r"(r1), "=r"(r2), "=r"(r3)
        : "r"(addr));
}
__device__ __forceinline__ uint32_t pack_h2(float x, float y) {
    __half2 h = __floats2half2_rn(x, y);
    return *(uint32_t*)&h;
}

// Ch[M,N] = half(A[M,K] @ B[K,N]); fused fp32 dots:
// as_out[m] += sum_c C[m,c]*av[c], ad_out[m] += sum_c C[m,c]*dv[c]
// BM=64, BN=128, WM=32, WN=32, 256 threads (8 warps 2x4)
template <typename TA>
__global__ __launch_bounds__(256, 3) void mma_gemm_kernel(
    const TA* __restrict__ A, const float* __restrict__ B,
    __half* __restrict__ Ch, const float* __restrict__ av,
    const float* __restrict__ dv, float* __restrict__ as_out,
    float* __restrict__ ad_out, int M, int N, int K) {
    constexpr int BM = 64, BN = 128, WM = 32, WN = 32;
    constexpr int GBK = 16;
    constexpr int RP = 24;     // A: halves per smem row (16 + 8 pad) = 48B
    constexpr int BROW = 136;  // B: halves per k-major row (128 + 8 pad) = 272B
    constexpr int WCOLS = BN / WN;  // 4
    constexpr int MI = WM / 16;     // 2
    constexpr int NJ = WN / 8;      // 4

    __shared__ __align__(16) __half As[2][BM][RP];     // m-major
    __shared__ __align__(16) __half Bs[2][GBK][BROW];  // k-major

    const int t = threadIdx.x;
    const int bm = blockIdx.y * BM;
    const int bn = blockIdx.x * BN;
    const int warp = t >> 5, lane = t & 31;
    const int g = lane >> 2, t4 = lane & 3;
    const int wm = (warp / WCOLS) * WM, wn = (warp % WCOLS) * WN;

    // ldmatrix lane addresses
    const uint32_t aBase = (uint32_t)__cvta_generic_to_shared(&As[0][0][0]);
    const uint32_t bBase = (uint32_t)__cvta_generic_to_shared(&Bs[0][0][0]);
    // A (non-trans): [m0-7/k0-7, m8-15/k0-7, m0-7/k8-15, m8-15/k8-15]
    const uint32_t aLane = aBase + (wm + (lane & 15)) * 48 + (lane & 16);
    // B (trans, k-major): row k = lane&15, col n = wn + 8*((lane&16)>>4)
    const uint32_t bLane =
        bBase + (lane & 15) * (BROW * 2) + (wn + ((lane & 16) >> 1)) * 2;
    constexpr uint32_t AsBytes = BM * RP * 2;
    constexpr uint32_t BsBytes = GBK * BROW * 2;

    // gmem staging: A = 4 elems/thread (row t>>2, cols (t&3)*4)
    // B = 2 float4/thread: rows k = warp, warp+8 ; cols 4*lane..+3
    const int arow = t >> 2, acol = (t & 3) * 4;
    const int bnq = (t & 31) * 4;

    float4 paf;     // TA=float staging
    uint2 pah;      // TA=half staging
    float4 pb4[2];

    auto ldg = [&](int k0) {
        int gr = bm + arow;
        if constexpr (sizeof(TA) == 4) {
            paf = (gr < M)
                      ? *(const float4*)((const float*)A + (size_t)gr * K + k0 + acol)
                      : make_float4(0.f, 0.f, 0.f, 0.f);
        } else {
            pah = (gr < M)
                      ? *(const uint2*)((const __half*)A + (size_t)gr * K + k0 + acol)
                      : make_uint2(0u, 0u);
        }
#pragma unroll
        for (int r = 0; r < 2; r++)
            pb4[r] = *(const float4*)(B + (size_t)(k0 + warp + 8 * r) * N + bn + bnq);
    };
    auto sts = [&](int s) {
        if constexpr (sizeof(TA) == 4) {
            uint2 u;
            u.x = pack_h2(paf.x, paf.y);
            u.y = pack_h2(paf.z, paf.w);
            *(uint2*)&As[s][arow][acol] = u;
        } else {
            *(uint2*)&As[s][arow][acol] = pah;
        }
#pragma unroll
        for (int r = 0; r < 2; r++) {
            uint2 u;
            u.x = pack_h2(pb4[r].x, pb4[r].y);
            u.y = pack_h2(pb4[r].z, pb4[r].w);
            *(uint2*)&Bs[s][warp + 8 * r][bnq] = u;
        }
    };

    float acc[MI][NJ][4];
#pragma unroll
    for (int i = 0; i < MI; i++)
#pragma unroll
        for (int j = 0; j < NJ; j++)
#pragma unroll
            for (int r = 0; r < 4; r++) acc[i][j][r] = 0.f;

    const int nIter = K / GBK;
    ldg(0);
    sts(0);
    __syncthreads();

    for (int it = 0; it < nIter; it++) {
        const int s = it & 1;
        if (it + 1 < nIter) ldg((it + 1) * GBK);
        const uint32_t aBuf = aLane + s * AsBytes;
        const uint32_t bBuf = bLane + s * BsBytes;
        uint32_t af[MI][4], bf[NJ][2];
#pragma unroll
        for (int i = 0; i < MI; i++)
            ldsm_x4(af[i][0], af[i][1], af[i][2], af[i][3], aBuf + i * 16 * 48);
#pragma unroll
        for (int j2 = 0; j2 < NJ / 2; j2++)
            ldsm_x4_trans(bf[2 * j2][0], bf[2 * j2][1], bf[2 * j2 + 1][0],
                          bf[2 * j2 + 1][1], bBuf + j2 * 32);
#pragma unroll
        for (int i = 0; i < MI; i++)
#pragma unroll
            for (int j = 0; j < NJ; j++) mma_f16(acc[i][j], af[i], bf[j]);
        if (it + 1 < nIter) {
            sts(s ^ 1);
            __syncthreads();
        }
    }

    // epilogue: half store + fused partial dots into as/ad via atomics
#pragma unroll
    for (int i = 0; i < MI; i++) {
        int r0 = bm + wm + i * 16 + g;
        int r1 = r0 + 8;
        float s0 = 0.f, d0 = 0.f, s1 = 0.f, d1 = 0.f;
#pragma unroll
        for (int j = 0; j < NJ; j++) {
            int c = bn + wn + j * 8 + 2 * t4;
            float a0 = av[c], a1 = av[c + 1];
            float e0 = dv[c], e1 = dv[c + 1];
            s0 += acc[i][j][0] * a0 + acc[i][j][1] * a1;
            d0 += acc[i][j][0] * e0 + acc[i][j][1] * e1;
            s1 += acc[i][j][2] * a0 + acc[i][j][3] * a1;
            d1 += acc[i][j][2] * e0 + acc[i][j][3] * e1;
            if (r0 < M)
                *(__half2*)(Ch + (size_t)r0 * N + c) =
                    __floats2half2_rn(acc[i][j][0], acc[i][j][1]);
            if (r1 < M)
                *(__half2*)(Ch + (size_t)r1 * N + c) =
                    __floats2half2_rn(acc[i][j][2], acc[i][j][3]);
        }
#pragma unroll
        for (int o = 1; o < 4; o <<= 1) {
            s0 += __shfl_xor_sync(~0u, s0, o);
            d0 += __shfl_xor_sync(~0u, d0, o);
            s1 += __shfl_xor_sync(~0u, s1, o);
            d1 += __shfl_xor_sync(~0u, d1, o);
        }
        if (t4 == 0) {
            if (r0 < M) {
                atomicAdd(&as_out[r0], s0);
                atomicAdd(&ad_out[r0], d0);
            }
            if (r1 < M) {
                atomicAdd(&as_out[r1], s1);
                atomicAdd(&ad_out[r1], d1);
            }
        }
    }
}

__device__ __forceinline__ float leaky(float x) {
    return fmaxf(x, NEG_SLOPE * x);
}

// -------- warp-per-node fused alpha + softmax + fp16 gather aggregation ----
template <int C, bool RELU, typename TOUT>
__global__ void aggregate_kernel(const __half* __restrict__ hh,
                                 const float* __restrict__ bias,
                                 TOUT* __restrict__ out,
                                 const float* __restrict__ asv,
                                 const float* __restrict__ adv,
                                 const float* __restrict__ aev, int N,
                                 int layer) {
    int warp = (blockIdx.x * blockDim.x + threadIdx.x) >> 5;
    int lane = threadIdx.x & 31;
    if (warp >= N) return;
    const int n = warp;
    const int rs = d_row[n], re = d_row[n + 1];
    const float adn = adv[n];
    float eself = __expf(leaky(asv[n] + adn + d_loopae[layer]));
    // pass 1: per-edge exp(leaky(logit)), lane-parallel; logits are O(1)
    float ssum = 0.f;
    for (int j = rs + lane; j < re; j += 32) {
        int s = d_csr_src[j];
        float ex = __expf(leaky(asv[s] + aev[j] + adn));
        d_alpha[j] = ex;
        ssum += ex;
    }
    for (int o = 16; o; o >>= 1) ssum += __shfl_xor_sync(~0u, ssum, o);
    __syncwarp();  // fence d_alpha stores before cross-lane reads
    float inv = 1.f / (ssum + eself);

    constexpr int NH2 = C / 64;  // half2 per lane (4 for C=256, 2 for C=128)
    float acc[2 * NH2];
    union U4 { uint4 v; __half2 h2[4]; };
    union U2 { uint2 v; __half2 h2[2]; };

    auto accum = [&](int s, float w) {
        if constexpr (C == 256) {
            U4 r; r.v = ((const uint4*)(hh + (size_t)s * C))[lane];
#pragma unroll
            for (int k = 0; k < 4; k++) {
                float2 f = __half22float2(r.h2[k]);
                acc[2 * k] += w * f.x;
                acc[2 * k + 1] += w * f.y;
            }
        } else {
            U2 r; r.v = ((const uint2*)(hh + (size_t)s * C))[lane];
#pragma unroll
            for (int k = 0; k < 2; k++) {
                float2 f = __half22float2(r.h2[k]);
                acc[2 * k] += w * f.x;
                acc[2 * k + 1] += w * f.y;
            }
        }
    };

#pragma unroll
    for (int k = 0; k < 2 * NH2; k++) acc[k] = 0.f;
    accum(n, eself * inv);  // self loop

    // 4x unrolled edge loop -> gather MLP=4
    int j = rs;
    for (; j + 4 <= re; j += 4) {
        float w0 = d_alpha[j] * inv, w1 = d_alpha[j + 1] * inv;
        float w2 = d_alpha[j + 2] * inv, w3 = d_alpha[j + 3] * inv;
        int s0 = d_csr_src[j], s1 = d_csr_src[j + 1];
        int s2 = d_csr_src[j + 2], s3 = d_csr_src[j + 3];
        if constexpr (C == 256) {
            U4 r0, r1, r2, r3;
            r0.v = ((const uint4*)(hh + (size_t)s0 * C))[lane];
            r1.v = ((const uint4*)(hh + (size_t)s1 * C))[lane];
            r2.v = ((const uint4*)(hh + (size_t)s2 * C))[lane];
            r3.v = ((const uint4*)(hh + (size_t)s3 * C))[lane];
#pragma unroll
            for (int k = 0; k < 4; k++) {
                float2 f0 = __half22float2(r0.h2[k]);
                float2 f1 = __half22float2(r1.h2[k]);
                float2 f2 = __half22float2(r2.h2[k]);
                float2 f3 = __half22float2(r3.h2[k]);
                acc[2 * k] += w0 * f0.x + w1 * f1.x + w2 * f2.x + w3 * f3.x;
                acc[2 * k + 1] +=
                    w0 * f0.y + w1 * f1.y + w2 * f2.y + w3 * f3.y;
            }
        } else {
            U2 r0, r1, r2, r3;
            r0.v = ((const uint2*)(hh + (size_t)s0 * C))[lane];
            r1.v = ((const uint2*)(hh + (size_t)s1 * C))[lane];
            r2.v = ((const uint2*)(hh + (size_t)s2 * C))[lane];
            r3.v = ((const uint2*)(hh + (size_t)s3 * C))[lane];
#pragma unroll
            for (int k = 0; k < 2; k++) {
                float2 f0 = __half22float2(r0.h2[k]);
                float2 f1 = __half22float2(r1.h2[k]);
                float2 f2 = __half22float2(r2.h2[k]);
                float2 f3 = __half22float2(r3.h2[k]);
                acc[2 * k] += w0 * f0.x + w1 * f1.x + w2 * f2.x + w3 * f3.x;
                acc[2 * k + 1] +=
                    w0 * f0.y + w1 * f1.y + w2 * f2.y + w3 * f3.y;
            }
        }
    }
    for (; j < re; j++) accum(d_csr_src[j], d_alpha[j] * inv);

    // write out: lane owns columns [lane*2*NH2, +2*NH2)
    const int base = lane * 2 * NH2;
    const float* bp = bias + base;
    float vv[2 * NH2];
#pragma unroll
    for (int k = 0; k < 2 * NH2; k++) {
        vv[k] = acc[k] + bp[k];
        if (RELU) vv[k] = fmaxf(vv[k], 0.f);
    }
    if constexpr (sizeof(TOUT) == 2) {
        __half2* op = (__half2*)((__half*)out + (size_t)n * C + base);
#pragma unroll
        for (int k = 0; k < NH2; k++)
            op[k] = __floats2half2_rn(vv[2 * k], vv[2 * k + 1]);
    } else {
        float* op = (float*)out + (size_t)n * C + base;
#pragma unroll
        for (int k = 0; k < 2 * NH2; k += 4)
            *(float4*)(op + k) =
                make_float4(vv[k], vv[k + 1], vv[k + 2], vv[k + 3]);
    }
}

// ---------------- launch ----------------------------------------------------
extern "C" void kernel_launch(void* const* d_in, const int* in_sizes, int n_in,
                              void* d_out, int out_size) {
    const float* x   = (const float*)d_in[0];
    const int*   ei  = (const int*)d_in[1];
    const float* ea  = (const float*)d_in[2];
    const float* W1  = (const float*)d_in[3];
    const float* We1 = (const float*)d_in[4];
    const float* as1 = (const float*)d_in[5];
    const float* ad1 = (const float*)d_in[6];
    const float* ae1 = (const float*)d_in[7];
    const float* b1  = (const float*)d_in[8];
    const float* W2  = (const float*)d_in[9];
    const float* We2 = (const float*)d_in[10];
    const float* as2 = (const float*)d_in[11];
    const float* ad2 = (const float*)d_in[12];
    const float* ae2 = (const float*)d_in[13];
    const float* b2  = (const float*)d_in[14];
    float* out = (float*)d_out;

    const int E = in_sizes[2] / ED;
    const int N = in_sizes[0] / CIN;
    const int* srcp = ei;
    const int* dstp = ei + E;

    void* p;
    cudaGetSymbolAddress(&p, d_hh);   __half* hhp  = (__half*)p;
    cudaGetSymbolAddress(&p, d_hid);  __half* hidp = (__half*)p;
    cudaGetSymbolAddress(&p, d_aev1); float* aev1p = (float*)p;
    cudaGetSymbolAddress(&p, d_aev2); float* aev2p = (float*)p;
    cudaGetSymbolAddress(&p, d_as1);  float* as1p  = (float*)p;
    cudaGetSymbolAddress(&p, d_ad1);  float* ad1p  = (float*)p;
    cudaGetSymbolAddress(&p, d_as2);  float* as2p  = (float*)p;
    cudaGetSymbolAddress(&p, d_ad2);  float* ad2p  = (float*)p;

    const int TPB = 256;
    const int warpsPerBlock = TPB / 32;
    const int nodeBlocks = (N + warpsPerBlock - 1) / warpsPerBlock;
    const int mBlocks = (N + 63) / 64;

    // 1-3: structure build prologue (zero_v NEEDS 512 threads: 16 warps for v)
    zero_v_kernel<<<128, 512>>>(We1, ae1, We2, ae2, N);
    hist_kernel<<<512, TPB>>>(dstp, ea, E);
    scan_kernel<<<1, 1024>>>(N, 1.f / (float)E);

    // 4: layer-1 GEMM (fp16 mma, +fused dots) — 4th launch for ncu
    mma_gemm_kernel<float><<<dim3(CHID / 128, mBlocks), 256>>>(
        x, W1, hhp, as1, ad1, as1p, ad1p, N, CHID, CIN);

    // 5: CSR scatter (independent of GEMM)
    scatter_kernel<<<512, TPB>>>(srcp, dstp, E);

    // 6: layer-1 fused alpha+softmax+aggregate -> fp16 hidden
    aggregate_kernel<CHID, true, __half><<<nodeBlocks, TPB>>>(
        hhp, b1, hidp, as1p, ad1p, aev1p, N, 0);

    // 7: layer-2 GEMM (fp16 A input, +fused dots)
    mma_gemm_kernel<__half><<<dim3(COUT / 128, mBlocks), 256>>>(
        hidp, W2, hhp, as2, ad2, as2p, ad2p, N, COUT, CHID);

    // 8: layer-2 fused aggregate -> fp32 output
    aggregate_kernel<COUT, false, float><<<nodeBlocks, TPB>>>(
        hhp, b2, out, as2p, ad2p, aev2p, N, 1);
}

// round 10
// speedup vs baseline: 1.5866x; 1.0068x over previous
#include <cuda_runtime.h>
#include <cuda_fp16.h>
#include <cstdint>

#define NEG_SLOPE 0.2f

static constexpr int MAXN = 50000;
static constexpr int MAXE = 800000;
static constexpr int CIN  = 128;
static constexpr int CHID = 256;
static constexpr int COUT = 128;
static constexpr int ED   = 8;

// ---------------- scratch (static device globals; no allocation allowed) ---
__device__ int    d_deg[MAXN];
__device__ int    d_row[MAXN + 1];
__device__ int    d_cur[MAXN];
__device__ int4   d_edge[MAXE];     // CSR: {src, bits(aev1), bits(aev2), 0}
__device__ float2 d_tmpab[MAXE];    // edge-ordered (aev1, aev2)
__device__ float  d_alpha[MAXE];    // exp(leaky(logit)) per CSR edge
__device__ __half d_xh[(size_t)MAXN * CIN];    // fp16 x
__device__ __half d_w1h[CIN * CHID];           // fp16 W1
__device__ __half d_w2h[CHID * COUT];          // fp16 W2
__device__ __half d_hh[(size_t)MAXN * CHID];   // transformed feats (fp16)
__device__ __half d_hid[(size_t)MAXN * CHID];  // relu(layer1 out) (fp16)
__device__ float  d_as1[MAXN];
__device__ float  d_ad1[MAXN];
__device__ float  d_as2[MAXN];
__device__ float  d_ad2[MAXN];
__device__ float  d_easum[ED];
__device__ float  d_v[2][ED];
__device__ float  d_loopae[2];

__device__ __forceinline__ uint32_t pack_h2(float x, float y) {
    __half2 h = __floats2half2_rn(x, y);
    return *(uint32_t*)&h;
}

// ------- prepass: fp16 convert x/W1/W2 + zero accumulators -----------------
__global__ void prep_kernel(const float* __restrict__ x,
                            const float* __restrict__ W1,
                            const float* __restrict__ W2, int n) {
    const int tid = blockIdx.x * blockDim.x + threadIdx.x;
    const int stride = gridDim.x * blockDim.x;
    const int nx4 = n * CIN / 4;
    for (int i = tid; i < nx4; i += stride) {
        float4 v = ((const float4*)x)[i];
        uint2 u;
        u.x = pack_h2(v.x, v.y);
        u.y = pack_h2(v.z, v.w);
        ((uint2*)d_xh)[i] = u;
    }
    for (int i = tid; i < CIN * CHID / 4; i += stride) {
        float4 v = ((const float4*)W1)[i];
        uint2 u;
        u.x = pack_h2(v.x, v.y);
        u.y = pack_h2(v.z, v.w);
        ((uint2*)d_w1h)[i] = u;
    }
    for (int i = tid; i < CHID * COUT / 4; i += stride) {
        float4 v = ((const float4*)W2)[i];
        uint2 u;
        u.x = pack_h2(v.x, v.y);
        u.y = pack_h2(v.z, v.w);
        ((uint2*)d_w2h)[i] = u;
    }
    for (int i = tid; i < n; i += stride) {
        d_deg[i] = 0;
        d_as1[i] = 0.f; d_ad1[i] = 0.f;
        d_as2[i] = 0.f; d_ad2[i] = 0.f;
    }
    if (tid < ED) d_easum[tid] = 0.f;
}

// ------- v[l] = We_l @ ae_l (one block, 512 threads = 16 warps) ------------
__global__ void vcomp_kernel(const float* __restrict__ We1,
                             const float* __restrict__ ae1,
                             const float* __restrict__ We2,
                             const float* __restrict__ ae2) {
    int wid = threadIdx.x >> 5, lane = threadIdx.x & 31;
    if (wid < ED) {
        float s = 0.f;
        for (int c = lane; c < CHID; c += 32) s += We1[wid * CHID + c] * ae1[c];
        for (int o = 16; o; o >>= 1) s += __shfl_xor_sync(~0u, s, o);
        if (!lane) d_v[0][wid] = s;
    } else if (wid < 2 * ED) {
        int r = wid - ED;
        float s = 0.f;
        for (int c = lane; c < COUT; c += 32) s += We2[r * COUT + c] * ae2[c];
        for (int o = 16; o; o >>= 1) s += __shfl_xor_sync(~0u, s, o);
        if (!lane) d_v[1][r] = s;
    }
}

// histogram of dst degrees + easum + per-edge attr attention (grid-stride)
__global__ void hist_kernel(const int* __restrict__ dstp,
                            const float* __restrict__ ea, int E) {
    __shared__ float ss[ED];
    if (threadIdx.x < ED) ss[threadIdx.x] = 0.f;
    __syncthreads();
    float v1[ED], v2[ED];
#pragma unroll
    for (int k = 0; k < ED; k++) { v1[k] = d_v[0][k]; v2[k] = d_v[1][k]; }
    float ls[ED] = {};
    for (int i = blockIdx.x * blockDim.x + threadIdx.x; i < E;
         i += gridDim.x * blockDim.x) {
        atomicAdd(&d_deg[dstp[i]], 1);
        const float4* p = (const float4*)(ea + (size_t)i * ED);
        float4 a = p[0], b = p[1];
        ls[0] += a.x; ls[1] += a.y; ls[2] += a.z; ls[3] += a.w;
        ls[4] += b.x; ls[5] += b.y; ls[6] += b.z; ls[7] += b.w;
        float t1 = a.x * v1[0] + a.y * v1[1] + a.z * v1[2] + a.w * v1[3] +
                   b.x * v1[4] + b.y * v1[5] + b.z * v1[6] + b.w * v1[7];
        float t2 = a.x * v2[0] + a.y * v2[1] + a.z * v2[2] + a.w * v2[3] +
                   b.x * v2[4] + b.y * v2[5] + b.z * v2[6] + b.w * v2[7];
        d_tmpab[i] = make_float2(t1, t2);
    }
#pragma unroll
    for (int k = 0; k < ED; k++) atomicAdd(&ss[k], ls[k]);
    __syncthreads();
    if (threadIdx.x < ED) atomicAdd(&d_easum[threadIdx.x], ss[threadIdx.x]);
}

// single-block exclusive scan of d_deg -> d_row / d_cur ; + loopae
__global__ void scan_kernel(int n, float Einv) {
    __shared__ int partial[1024];
    const int t = threadIdx.x;
    const int CHK = (n + 1023) / 1024;
    int start = t * CHK;
    int end = start + CHK; if (end > n) end = n;
    int s = 0;
    for (int i = start; i < end; i++) s += d_deg[i];
    partial[t] = s;
    __syncthreads();
    for (int off = 1; off < 1024; off <<= 1) {
        int v = (t >= off) ? partial[t - off] : 0;
        __syncthreads();
        partial[t] += v;
        __syncthreads();
    }
    int run = (t == 0) ? 0 : partial[t - 1];
    for (int i = start; i < end; i++) {
        d_row[i] = run;
        d_cur[i] = run;
        run += d_deg[i];
    }
    if (t == 1023) d_row[n] = partial[1023];
    if (t < 2) {
        float la = 0.f;
#pragma unroll
        for (int i = 0; i < ED; i++) la += d_easum[i] * Einv * d_v[t][i];
        d_loopae[t] = la;
    }
}

// scatter edges into CSR-by-dst; ONE int4 store per edge; atomic MLP=4
__global__ void scatter_kernel(const int* __restrict__ srcp,
                               const int* __restrict__ dstp, int E) {
    const int st = gridDim.x * blockDim.x;
    for (int e = blockIdx.x * blockDim.x + threadIdx.x; e < E; e += 4 * st) {
        int e1 = e + st, e2 = e + 2 * st, e3 = e + 3 * st;
        bool v1 = e1 < E, v2 = e2 < E, v3 = e3 < E;
        int d0 = dstp[e];
        int d1 = v1 ? dstp[e1] : 0;
        int d2 = v2 ? dstp[e2] : 0;
        int d3 = v3 ? dstp[e3] : 0;
        int p0 = atomicAdd(&d_cur[d0], 1);
        int p1 = v1 ? atomicAdd(&d_cur[d1], 1) : 0;
        int p2 = v2 ? atomicAdd(&d_cur[d2], 1) : 0;
        int p3 = v3 ? atomicAdd(&d_cur[d3], 1) : 0;
        float2 t0 = d_tmpab[e];
        d_edge[p0] = make_int4(srcp[e], __float_as_int(t0.x),
                               __float_as_int(t0.y), 0);
        if (v1) {
            float2 t = d_tmpab[e1];
            d_edge[p1] = make_int4(srcp[e1], __float_as_int(t.x),
                                   __float_as_int(t.y), 0);
        }
        if (v2) {
            float2 t = d_tmpab[e2];
            d_edge[p2] = make_int4(srcp[e2], __float_as_int(t.x),
                                   __float_as_int(t.y), 0);
        }
        if (v3) {
            float2 t = d_tmpab[e3];
            d_edge[p3] = make_int4(srcp[e3], __float_as_int(t.x),
                                   __float_as_int(t.y), 0);
        }
    }
}

// ---------------- fp16 tensor-core GEMM (m16n8k16, fp32 acc) ---------------
__device__ __forceinline__ void mma_f16(float* d, const uint32_t* a,
                                        const uint32_t* b) {
    asm volatile(
        "mma.sync.aligned.m16n8k16.row.col.f32.f16.f16.f32 "
        "{%0,%1,%2,%3}, {%4,%5,%6,%7}, {%8,%9}, {%0,%1,%2,%3};\n"
        : "+f"(d[0]), "+f"(d[1]), "+f"(d[2]), "+f"(d[3])
        : "r"(a[0]), "r"(a[1]), "r"(a[2]), "r"(a[3]), "r"(b[0]), "r"(b[1]));
}
__device__ __forceinline__ void ldsm_x4(uint32_t& r0, uint32_t& r1,
                                        uint32_t& r2, uint32_t& r3,
                                        uint32_t addr) {
    asm volatile(
        "ldmatrix.sync.aligned.m8n8.x4.shared.b16 {%0,%1,%2,%3}, [%4];"
        : "=r"(r0), "=r"(r1), "=r"(r2), "=r"(r3)
        : "r"(addr));
}
__device__ __forceinline__ void ldsm_x4_trans(uint32_t& r0, uint32_t& r1,
                                              uint32_t& r2, uint32_t& r3,
                                              uint32_t addr) {
    asm volatile(
        "ldmatrix.sync.aligned.m8n8.x4.trans.shared.b16 {%0,%1,%2,%3}, [%4];"
        : "=r"(r0), "=r"(r1), "=r"(r2), "=r"(r3)
        : "r"(addr));
}

// Ch[M,N] = half(A[M,K] @ B[K,N]); A,B fp16 row-major; fused fp32 dots.
// BM=64, BN=128, WM=32, WN=32, 256 threads (8 warps 2x4)
__global__ __launch_bounds__(256, 3) void mma_gemm_kernel(
    const __half* __restrict__ A, const __half* __restrict__ B,
    __half* __restrict__ Ch, const float* __restrict__ av,
    const float* __restrict__ dv, float* __restrict__ as_out,
    float* __restrict__ ad_out, int M, int N, int K) {
    constexpr int BM = 64, BN = 128, WM = 32, WN = 32;
    constexpr int GBK = 16;
    constexpr int RP = 24;     // A: halves per smem row (16 + 8 pad) = 48B
    constexpr int BROW = 136;  // B: halves per k-major row (128 + 8 pad)
    constexpr int WCOLS = BN / WN;  // 4
    constexpr int MI = WM / 16;     // 2
    constexpr int NJ = WN / 8;      // 4

    __shared__ __align__(16) __half As[2][BM][RP];     // m-major
    __shared__ __align__(16) __half Bs[2][GBK][BROW];  // k-major

    const int t = threadIdx.x;
    const int bm = blockIdx.y * BM;
    const int bn = blockIdx.x * BN;
    const int warp = t >> 5, lane = t & 31;
    const int g = lane >> 2, t4 = lane & 3;
    const int wm = (warp / WCOLS) * WM, wn = (warp % WCOLS) * WN;

    const uint32_t aBase = (uint32_t)__cvta_generic_to_shared(&As[0][0][0]);
    const uint32_t bBase = (uint32_t)__cvta_generic_to_shared(&Bs[0][0][0]);
    const uint32_t aLane = aBase + (wm + (lane & 15)) * 48 + (lane & 16);
    const uint32_t bLane =
        bBase + (lane & 15) * (BROW * 2) + (wn + ((lane & 16) >> 1)) * 2;
    constexpr uint32_t AsBytes = BM * RP * 2;
    constexpr uint32_t BsBytes = GBK * BROW * 2;

    // staging: A uint2 (4 halves)/thread; B uint4 (8 halves)/thread
    const int arow = t >> 2, acol = (t & 3) * 4;
    const int bkr = t >> 4, bcol = (t & 15) * 8;

    uint2 pah;
    uint4 pbu;
    auto ldg = [&](int k0) {
        int gr = bm + arow;
        pah = (gr < M) ? *(const uint2*)(A + (size_t)gr * K + k0 + acol)
                       : make_uint2(0u, 0u);
        pbu = *(const uint4*)(B + (size_t)(k0 + bkr) * N + bn + bcol);
    };
    auto sts = [&](int s) {
        *(uint2*)&As[s][arow][acol] = pah;
        *(uint4*)&Bs[s][bkr][bcol] = pbu;
    };

    float acc[MI][NJ][4];
#pragma unroll
    for (int i = 0; i < MI; i++)
#pragma unroll
        for (int j = 0; j < NJ; j++)
#pragma unroll
            for (int r = 0; r < 4; r++) acc[i][j][r] = 0.f;

    const int nIter = K / GBK;
    ldg(0);
    sts(0);
    __syncthreads();

    for (int it = 0; it < nIter; it++) {
        const int s = it & 1;
        if (it + 1 < nIter) ldg((it + 1) * GBK);
        const uint32_t aBuf = aLane + s * AsBytes;
        const uint32_t bBuf = bLane + s * BsBytes;
        uint32_t af[MI][4], bf[NJ][2];
#pragma unroll
        for (int i = 0; i < MI; i++)
            ldsm_x4(af[i][0], af[i][1], af[i][2], af[i][3], aBuf + i * 16 * 48);
#pragma unroll
        for (int j2 = 0; j2 < NJ / 2; j2++)
            ldsm_x4_trans(bf[2 * j2][0], bf[2 * j2][1], bf[2 * j2 + 1][0],
                          bf[2 * j2 + 1][1], bBuf + j2 * 32);
#pragma unroll
        for (int i = 0; i < MI; i++)
#pragma unroll
            for (int j = 0; j < NJ; j++) mma_f16(acc[i][j], af[i], bf[j]);
        if (it + 1 < nIter) {
            sts(s ^ 1);
            __syncthreads();
        }
    }

    // epilogue: half store + fused partial dots into as/ad via atomics
#pragma unroll
    for (int i = 0; i < MI; i++) {
        int r0 = bm + wm + i * 16 + g;
        int r1 = r0 + 8;
        float s0 = 0.f, d0 = 0.f, s1 = 0.f, d1 = 0.f;
#pragma unroll
        for (int j = 0; j < NJ; j++) {
            int c = bn + wn + j * 8 + 2 * t4;
            float a0 = av[c], a1 = av[c + 1];
            float e0 = dv[c], e1 = dv[c + 1];
            s0 += acc[i][j][0] * a0 + acc[i][j][1] * a1;
            d0 += acc[i][j][0] * e0 + acc[i][j][1] * e1;
            s1 += acc[i][j][2] * a0 + acc[i][j][3] * a1;
            d1 += acc[i][j][2] * e0 + acc[i][j][3] * e1;
            if (r0 < M)
                *(__half2*)(Ch + (size_t)r0 * N + c) =
                    __floats2half2_rn(acc[i][j][0], acc[i][j][1]);
            if (r1 < M)
                *(__half2*)(Ch + (size_t)r1 * N + c) =
                    __floats2half2_rn(acc[i][j][2], acc[i][j][3]);
        }
#pragma unroll
        for (int o = 1; o < 4; o <<= 1) {
            s0 += __shfl_xor_sync(~0u, s0, o);
            d0 += __shfl_xor_sync(~0u, d0, o);
            s1 += __shfl_xor_sync(~0u, s1, o);
            d1 += __shfl_xor_sync(~0u, d1, o);
        }
        if (t4 == 0) {
            if (r0 < M) {
                atomicAdd(&as_out[r0], s0);
                atomicAdd(&ad_out[r0], d0);
            }
            if (r1 < M) {
                atomicAdd(&as_out[r1], s1);
                atomicAdd(&ad_out[r1], d1);
            }
        }
    }
}

__device__ __forceinline__ float leaky(float x) {
    return fmaxf(x, NEG_SLOPE * x);
}

// -------- warp-per-node fused alpha + softmax + fp16 gather aggregation ----
// C==256 -> layer 1 (aev = edge.y), C==128 -> layer 2 (aev = edge.z)
template <int C, bool RELU, typename TOUT>
__global__ void aggregate_kernel(const __half* __restrict__ hh,
                                 const float* __restrict__ bias,
                                 TOUT* __restrict__ out,
                                 const float* __restrict__ asv,
                                 const float* __restrict__ adv, int N) {
    int warp = (blockIdx.x * blockDim.x + threadIdx.x) >> 5;
    int lane = threadIdx.x & 31;
    if (warp >= N) return;
    const int n = warp;
    const int rs = d_row[n], re = d_row[n + 1];
    const float adn = adv[n];
    constexpr int LAYER = (C == 256) ? 0 : 1;
    float eself = __expf(leaky(asv[n] + adn + d_loopae[LAYER]));
    // pass 1: per-edge exp(leaky(logit)), lane-parallel; logits are O(1)
    float ssum = 0.f;
    for (int j = rs + lane; j < re; j += 32) {
        int4 e4 = d_edge[j];
        float aevj = (C == 256) ? __int_as_float(e4.y) : __int_as_float(e4.z);
        float ex = __expf(leaky(asv[e4.x] + aevj + adn));
        d_alpha[j] = ex;
        ssum += ex;
    }
    for (int o = 16; o; o >>= 1) ssum += __shfl_xor_sync(~0u, ssum, o);
    __syncwarp();  // fence d_alpha stores before cross-lane reads
    float inv = 1.f / (ssum + eself);

    constexpr int NH2 = C / 64;  // half2 per lane (4 for C=256, 2 for C=128)
    float acc[2 * NH2];
    union U4 { uint4 v; __half2 h2[4]; };
    union U2 { uint2 v; __half2 h2[2]; };

    auto accum = [&](int s, float w) {
        if constexpr (C == 256) {
            U4 r; r.v = ((const uint4*)(hh + (size_t)s * C))[lane];
#pragma unroll
            for (int k = 0; k < 4; k++) {
                float2 f = __half22float2(r.h2[k]);
                acc[2 * k] += w * f.x;
                acc[2 * k + 1] += w * f.y;
            }
        } else {
            U2 r; r.v = ((const uint2*)(hh + (size_t)s * C))[lane];
#pragma unroll
            for (int k = 0; k < 2; k++) {
                float2 f = __half22float2(r.h2[k]);
                acc[2 * k] += w * f.x;
                acc[2 * k + 1] += w * f.y;
            }
        }
    };

#pragma unroll
    for (int k = 0; k < 2 * NH2; k++) acc[k] = 0.f;
    accum(n, eself * inv);  // self loop

    // 4x unrolled edge loop -> gather MLP=4
    int j = rs;
    for (; j + 4 <= re; j += 4) {
        float w0 = d_alpha[j] * inv, w1 = d_alpha[j + 1] * inv;
        float w2 = d_alpha[j + 2] * inv, w3 = d_alpha[j + 3] * inv;
        int s0 = d_edge[j].x, s1 = d_edge[j + 1].x;
        int s2 = d_edge[j + 2].x, s3 = d_edge[j + 3].x;
        if constexpr (C == 256) {
            U4 r0, r1, r2, r3;
            r0.v = ((const uint4*)(hh + (size_t)s0 * C))[lane];
            r1.v = ((const uint4*)(hh + (size_t)s1 * C))[lane];
            r2.v = ((const uint4*)(hh + (size_t)s2 * C))[lane];
            r3.v = ((const uint4*)(hh + (size_t)s3 * C))[lane];
#pragma unroll
            for (int k = 0; k < 4; k++) {
                float2 f0 = __half22float2(r0.h2[k]);
                float2 f1 = __half22float2(r1.h2[k]);
                float2 f2 = __half22float2(r2.h2[k]);
                float2 f3 = __half22float2(r3.h2[k]);
                acc[2 * k] += w0 * f0.x + w1 * f1.x + w2 * f2.x + w3 * f3.x;
                acc[2 * k + 1] +=
                    w0 * f0.y + w1 * f1.y + w2 * f2.y + w3 * f3.y;
            }
        } else {
            U2 r0, r1, r2, r3;
            r0.v = ((const uint2*)(hh + (size_t)s0 * C))[lane];
            r1.v = ((const uint2*)(hh + (size_t)s1 * C))[lane];
            r2.v = ((const uint2*)(hh + (size_t)s2 * C))[lane];
            r3.v = ((const uint2*)(hh + (size_t)s3 * C))[lane];
#pragma unroll
            for (int k = 0; k < 2; k++) {
                float2 f0 = __half22float2(r0.h2[k]);
                float2 f1 = __half22float2(r1.h2[k]);
                float2 f2 = __half22float2(r2.h2[k]);
                float2 f3 = __half22float2(r3.h2[k]);
                acc[2 * k] += w0 * f0.x + w1 * f1.x + w2 * f2.x + w3 * f3.x;
                acc[2 * k + 1] +=
                    w0 * f0.y + w1 * f1.y + w2 * f2.y + w3 * f3.y;
            }
        }
    }
    for (; j < re; j++) accum(d_edge[j].x, d_alpha[j] * inv);

    // write out: lane owns columns [lane*2*NH2, +2*NH2)
    const int base = lane * 2 * NH2;
    const float* bp = bias + base;
    float vv[2 * NH2];
#pragma unroll
    for (int k = 0; k < 2 * NH2; k++) {
        vv[k] = acc[k] + bp[k];
        if (RELU) vv[k] = fmaxf(vv[k], 0.f);
    }
    if constexpr (sizeof(TOUT) == 2) {
        __half2* op = (__half2*)((__half*)out + (size_t)n * C + base);
#pragma unroll
        for (int k = 0; k < NH2; k++)
            op[k] = __floats2half2_rn(vv[2 * k], vv[2 * k + 1]);
    } else {
        float* op = (float*)out + (size_t)n * C + base;
#pragma unroll
        for (int k = 0; k < 2 * NH2; k += 4)
            *(float4*)(op + k) =
                make_float4(vv[k], vv[k + 1], vv[k + 2], vv[k + 3]);
    }
}

// ---------------- launch ----------------------------------------------------
extern "C" void kernel_launch(void* const* d_in, const int* in_sizes, int n_in,
                              void* d_out, int out_size) {
    const float* x   = (const float*)d_in[0];
    const int*   ei  = (const int*)d_in[1];
    const float* ea  = (const float*)d_in[2];
    const float* W1  = (const float*)d_in[3];
    const float* We1 = (const float*)d_in[4];
    const float* as1 = (const float*)d_in[5];
    const float* ad1 = (const float*)d_in[6];
    const float* ae1 = (const float*)d_in[7];
    const float* b1  = (const float*)d_in[8];
    const float* W2  = (const float*)d_in[9];
    const float* We2 = (const float*)d_in[10];
    const float* as2 = (const float*)d_in[11];
    const float* ad2 = (const float*)d_in[12];
    const float* ae2 = (const float*)d_in[13];
    const float* b2  = (const float*)d_in[14];
    float* out = (float*)d_out;

    const int E = in_sizes[2] / ED;
    const int N = in_sizes[0] / CIN;
    const int* srcp = ei;
    const int* dstp = ei + E;

    void* p;
    cudaGetSymbolAddress(&p, d_xh);   __half* xhp  = (__half*)p;
    cudaGetSymbolAddress(&p, d_w1h);  __half* w1hp = (__half*)p;
    cudaGetSymbolAddress(&p, d_w2h);  __half* w2hp = (__half*)p;
    cudaGetSymbolAddress(&p, d_hh);   __half* hhp  = (__half*)p;
    cudaGetSymbolAddress(&p, d_hid);  __half* hidp = (__half*)p;
    cudaGetSymbolAddress(&p, d_as1);  float* as1p  = (float*)p;
    cudaGetSymbolAddress(&p, d_ad1);  float* ad1p  = (float*)p;
    cudaGetSymbolAddress(&p, d_as2);  float* as2p  = (float*)p;
    cudaGetSymbolAddress(&p, d_ad2);  float* ad2p  = (float*)p;

    const int TPB = 256;
    const int warpsPerBlock = TPB / 32;
    const int nodeBlocks = (N + warpsPerBlock - 1) / warpsPerBlock;
    const int mBlocks = (N + 63) / 64;

    // 1: prepass (fp16 convert + zero)   2: v   3: hist   4: scatter-slot...
    prep_kernel<<<256, 512>>>(x, W1, W2, N);
    vcomp_kernel<<<1, 512>>>(We1, ae1, We2, ae2);
    hist_kernel<<<512, TPB>>>(dstp, ea, E);
    scan_kernel<<<1, 1024>>>(N, 1.f / (float)E);   // 4th launch: scan profiled

    // 5: CSR scatter
    scatter_kernel<<<512, TPB>>>(srcp, dstp, E);

    // 6: layer-1 GEMM (all-fp16 inputs, +fused dots)
    mma_gemm_kernel<<<dim3(CHID / 128, mBlocks), 256>>>(
        xhp, w1hp, hhp, as1, ad1, as1p, ad1p, N, CHID, CIN);

    // 7: layer-1 fused alpha+softmax+aggregate -> fp16 hidden
    aggregate_kernel<CHID, true, __half><<<nodeBlocks, TPB>>>(
        hhp, b1, hidp, as1p, ad1p, N);

    // 8: layer-2 GEMM (fp16 inputs, +fused dots)
    mma_gemm_kernel<<<dim3(COUT / 128, mBlocks), 256>>>(
        hidp, w2hp, hhp, as2, ad2, as2p, ad2p, N, COUT, CHID);

    // 9: layer-2 fused aggregate -> fp32 output
    aggregate_kernel<COUT, false, float><<<nodeBlocks, TPB>>>(
        hhp, b2, out, as2p, ad2p, N);
}

// round 11
// speedup vs baseline: 2.0959x; 1.3210x over previous
#include <cuda_runtime.h>
#include <cuda_fp16.h>
#include <cstdint>

#define NEG_SLOPE 0.2f

static constexpr int MAXN = 50000;
static constexpr int MAXE = 800000;
static constexpr int CIN  = 128;
static constexpr int CHID = 256;
static constexpr int COUT = 128;
static constexpr int ED   = 8;
static constexpr int SCAN_TPB = 256;
static constexpr int SCAN_NB  = (MAXN + SCAN_TPB - 1) / SCAN_TPB;  // 196

// ---------------- scratch (static device globals; no allocation allowed) ---
__device__ int    d_deg[MAXN];
__device__ int    d_row[MAXN + 1];
__device__ int    d_cur[MAXN];
__device__ int    d_bsum[SCAN_TPB];   // per-block deg sums (<=256 blocks)
__device__ int    d_boff[SCAN_TPB];   // exclusive block offsets
__device__ int4   d_edge[MAXE];       // CSR: {src, bits(aev1), bits(aev2), 0}
__device__ float2 d_tmpab[MAXE];      // edge-ordered (aev1, aev2)
__device__ float  d_alpha[MAXE];      // exp(leaky(logit)) per CSR edge
__device__ __half d_xh[(size_t)MAXN * CIN];    // fp16 x
__device__ __half d_w1h[CIN * CHID];           // fp16 W1
__device__ __half d_w2h[CHID * COUT];          // fp16 W2
__device__ __half d_hh[(size_t)MAXN * CHID];   // transformed feats (fp16)
__device__ __half d_hid[(size_t)MAXN * CHID];  // relu(layer1 out) (fp16)
__device__ float  d_as1[MAXN];
__device__ float  d_ad1[MAXN];
__device__ float  d_as2[MAXN];
__device__ float  d_ad2[MAXN];
__device__ float  d_easum[ED];
__device__ float  d_v[2][ED];
__device__ float  d_loopae[2];

__device__ __forceinline__ uint32_t pack_h2(float x, float y) {
    __half2 h = __floats2half2_rn(x, y);
    return *(uint32_t*)&h;
}

// ------- prepass: fp16 convert x/W1/W2 + zero accumulators -----------------
__global__ void prep_kernel(const float* __restrict__ x,
                            const float* __restrict__ W1,
                            const float* __restrict__ W2, int n) {
    const int tid = blockIdx.x * blockDim.x + threadIdx.x;
    const int stride = gridDim.x * blockDim.x;
    const int nx4 = n * CIN / 4;
    for (int i = tid; i < nx4; i += stride) {
        float4 v = ((const float4*)x)[i];
        uint2 u;
        u.x = pack_h2(v.x, v.y);
        u.y = pack_h2(v.z, v.w);
        ((uint2*)d_xh)[i] = u;
    }
    for (int i = tid; i < CIN * CHID / 4; i += stride) {
        float4 v = ((const float4*)W1)[i];
        uint2 u;
        u.x = pack_h2(v.x, v.y);
        u.y = pack_h2(v.z, v.w);
        ((uint2*)d_w1h)[i] = u;
    }
    for (int i = tid; i < CHID * COUT / 4; i += stride) {
        float4 v = ((const float4*)W2)[i];
        uint2 u;
        u.x = pack_h2(v.x, v.y);
        u.y = pack_h2(v.z, v.w);
        ((uint2*)d_w2h)[i] = u;
    }
    for (int i = tid; i < n; i += stride) {
        d_deg[i] = 0;
        d_as1[i] = 0.f; d_ad1[i] = 0.f;
        d_as2[i] = 0.f; d_ad2[i] = 0.f;
    }
    if (tid < ED) d_easum[tid] = 0.f;
}

// ------- v[l] = We_l @ ae_l (one block, 512 threads = 16 warps) ------------
__global__ void vcomp_kernel(const float* __restrict__ We1,
                             const float* __restrict__ ae1,
                             const float* __restrict__ We2,
                             const float* __restrict__ ae2) {
    int wid = threadIdx.x >> 5, lane = threadIdx.x & 31;
    if (wid < ED) {
        float s = 0.f;
        for (int c = lane; c < CHID; c += 32) s += We1[wid * CHID + c] * ae1[c];
        for (int o = 16; o; o >>= 1) s += __shfl_xor_sync(~0u, s, o);
        if (!lane) d_v[0][wid] = s;
    } else if (wid < 2 * ED) {
        int r = wid - ED;
        float s = 0.f;
        for (int c = lane; c < COUT; c += 32) s += We2[r * COUT + c] * ae2[c];
        for (int o = 16; o; o >>= 1) s += __shfl_xor_sync(~0u, s, o);
        if (!lane) d_v[1][r] = s;
    }
}

// histogram of dst degrees + easum + per-edge attr attention (grid-stride)
__global__ void hist_kernel(const int* __restrict__ dstp,
                            const float* __restrict__ ea, int E) {
    __shared__ float ss[ED];
    if (threadIdx.x < ED) ss[threadIdx.x] = 0.f;
    __syncthreads();
    float v1[ED], v2[ED];
#pragma unroll
    for (int k = 0; k < ED; k++) { v1[k] = d_v[0][k]; v2[k] = d_v[1][k]; }
    float ls[ED] = {};
    for (int i = blockIdx.x * blockDim.x + threadIdx.x; i < E;
         i += gridDim.x * blockDim.x) {
        atomicAdd(&d_deg[dstp[i]], 1);
        const float4* p = (const float4*)(ea + (size_t)i * ED);
        float4 a = p[0], b = p[1];
        ls[0] += a.x; ls[1] += a.y; ls[2] += a.z; ls[3] += a.w;
        ls[4] += b.x; ls[5] += b.y; ls[6] += b.z; ls[7] += b.w;
        float t1 = a.x * v1[0] + a.y * v1[1] + a.z * v1[2] + a.w * v1[3] +
                   b.x * v1[4] + b.y * v1[5] + b.z * v1[6] + b.w * v1[7];
        float t2 = a.x * v2[0] + a.y * v2[1] + a.z * v2[2] + a.w * v2[3] +
                   b.x * v2[4] + b.y * v2[5] + b.z * v2[6] + b.w * v2[7];
        d_tmpab[i] = make_float2(t1, t2);
    }
#pragma unroll
    for (int k = 0; k < ED; k++) atomicAdd(&ss[k], ls[k]);
    __syncthreads();
    if (threadIdx.x < ED) atomicAdd(&d_easum[threadIdx.x], ss[threadIdx.x]);
}

// ------- multi-block scan: p1 block sums, p2 scan of sums, p3 final --------
__global__ void scan_p1_kernel(int n) {
    int i = blockIdx.x * SCAN_TPB + threadIdx.x;
    int v = (i < n) ? d_deg[i] : 0;
    __shared__ int sh[SCAN_TPB / 32];
    for (int o = 16; o; o >>= 1) v += __shfl_xor_sync(~0u, v, o);
    if ((threadIdx.x & 31) == 0) sh[threadIdx.x >> 5] = v;
    __syncthreads();
    if (threadIdx.x < SCAN_TPB / 32) {
        int s = sh[threadIdx.x];
        for (int o = SCAN_TPB / 64; o; o >>= 1)
            s += __shfl_xor_sync((1u << (SCAN_TPB / 32)) - 1u, s, o);
        if (threadIdx.x == 0) d_bsum[blockIdx.x] = s;
    }
}

__global__ void scan_p2_kernel(int nb, int n, float Einv) {
    __shared__ int sh[SCAN_TPB];
    int t = threadIdx.x;
    int v = (t < nb) ? d_bsum[t] : 0;
    sh[t] = v;
    __syncthreads();
    for (int off = 1; off < SCAN_TPB; off <<= 1) {
        int u = (t >= off) ? sh[t - off] : 0;
        __syncthreads();
        sh[t] += u;
        __syncthreads();
    }
    d_boff[t] = sh[t] - v;  // exclusive
    if (t == SCAN_TPB - 1) d_row[n] = sh[SCAN_TPB - 1];
    if (t < 2) {
        float la = 0.f;
#pragma unroll
        for (int i = 0; i < ED; i++) la += d_easum[i] * Einv * d_v[t][i];
        d_loopae[t] = la;
    }
}

__global__ void scan_p3_kernel(int n) {
    __shared__ int sh[SCAN_TPB];
    int t = threadIdx.x;
    int i = blockIdx.x * SCAN_TPB + t;
    int v = (i < n) ? d_deg[i] : 0;
    sh[t] = v;
    __syncthreads();
    for (int off = 1; off < SCAN_TPB; off <<= 1) {
        int u = (t >= off) ? sh[t - off] : 0;
        __syncthreads();
        sh[t] += u;
        __syncthreads();
    }
    if (i < n) {
        int r = d_boff[blockIdx.x] + sh[t] - v;  // exclusive prefix
        d_row[i] = r;
        d_cur[i] = r;
    }
}

// scatter edges into CSR-by-dst; ONE int4 store per edge; atomic MLP=4
__global__ void scatter_kernel(const int* __restrict__ srcp,
                               const int* __restrict__ dstp, int E) {
    const int st = gridDim.x * blockDim.x;
    for (int e = blockIdx.x * blockDim.x + threadIdx.x; e < E; e += 4 * st) {
        int e1 = e + st, e2 = e + 2 * st, e3 = e + 3 * st;
        bool v1 = e1 < E, v2 = e2 < E, v3 = e3 < E;
        int d0 = dstp[e];
        int d1 = v1 ? dstp[e1] : 0;
        int d2 = v2 ? dstp[e2] : 0;
        int d3 = v3 ? dstp[e3] : 0;
        int p0 = atomicAdd(&d_cur[d0], 1);
        int p1 = v1 ? atomicAdd(&d_cur[d1], 1) : 0;
        int p2 = v2 ? atomicAdd(&d_cur[d2], 1) : 0;
        int p3 = v3 ? atomicAdd(&d_cur[d3], 1) : 0;
        float2 t0 = d_tmpab[e];
        d_edge[p0] = make_int4(srcp[e], __float_as_int(t0.x),
                               __float_as_int(t0.y), 0);
        if (v1) {
            float2 t = d_tmpab[e1];
            d_edge[p1] = make_int4(srcp[e1], __float_as_int(t.x),
                                   __float_as_int(t.y), 0);
        }
        if (v2) {
            float2 t = d_tmpab[e2];
            d_edge[p2] = make_int4(srcp[e2], __float_as_int(t.x),
                                   __float_as_int(t.y), 0);
        }
        if (v3) {
            float2 t = d_tmpab[e3];
            d_edge[p3] = make_int4(srcp[e3], __float_as_int(t.x),
                                   __float_as_int(t.y), 0);
        }
    }
}

// ---------------- fp16 tensor-core GEMM (m16n8k16, fp32 acc) ---------------
__device__ __forceinline__ void mma_f16(float* d, const uint32_t* a,
                                        const uint32_t* b) {
    asm volatile(
        "mma.sync.aligned.m16n8k16.row.col.f32.f16.f16.f32 "
        "{%0,%1,%2,%3}, {%4,%5,%6,%7}, {%8,%9}, {%0,%1,%2,%3};\n"
        : "+f"(d[0]), "+f"(d[1]), "+f"(d[2]), "+f"(d[3])
        : "r"(a[0]), "r"(a[1]), "r"(a[2]), "r"(a[3]), "r"(b[0]), "r"(b[1]));
}
__device__ __forceinline__ void ldsm_x4(uint32_t& r0, uint32_t& r1,
                                        uint32_t& r2, uint32_t& r3,
                                        uint32_t addr) {
    asm volatile(
        "ldmatrix.sync.aligned.m8n8.x4.shared.b16 {%0,%1,%2,%3}, [%4];"
        : "=r"(r0), "=r"(r1), "=r"(r2), "=r"(r3)
        : "r"(addr));
}
__device__ __forceinline__ void ldsm_x4_trans(uint32_t& r0, uint32_t& r1,
                                              uint32_t& r2, uint32_t& r3,
                                              uint32_t addr) {
    asm volatile(
        "ldmatrix.sync.aligned.m8n8.x4.trans.shared.b16 {%0,%1,%2,%3}, [%4];"
        : "=r"(r0), "=r"(r1), "=r"(r2), "=r"(r3)
        : "r"(addr));
}

// Ch[M,N] = half(A[M,K] @ B[K,N]); A,B fp16 row-major; fused fp32 dots.
// BM=64, BN=128, WM=32, WN=32, 256 threads (8 warps 2x4)
__global__ __launch_bounds__(256, 3) void mma_gemm_kernel(
    const __half* __restrict__ A, const __half* __restrict__ B,
    __half* __restrict__ Ch, const float* __restrict__ av,
    const float* __restrict__ dv, float* __restrict__ as_out,
    float* __restrict__ ad_out, int M, int N, int K) {
    constexpr int BM = 64, BN = 128, WM = 32, WN = 32;
    constexpr int GBK = 16;
    constexpr int RP = 24;     // A: halves per smem row (16 + 8 pad) = 48B
    constexpr int BROW = 136;  // B: halves per k-major row (128 + 8 pad)
    constexpr int WCOLS = BN / WN;  // 4
    constexpr int MI = WM / 16;     // 2
    constexpr int NJ = WN / 8;      // 4

    __shared__ __align__(16) __half As[2][BM][RP];     // m-major
    __shared__ __align__(16) __half Bs[2][GBK][BROW];  // k-major

    const int t = threadIdx.x;
    const int bm = blockIdx.y * BM;
    const int bn = blockIdx.x * BN;
    const int warp = t >> 5, lane = t & 31;
    const int g = lane >> 2, t4 = lane & 3;
    const int wm = (warp / WCOLS) * WM, wn = (warp % WCOLS) * WN;

    const uint32_t aBase = (uint32_t)__cvta_generic_to_shared(&As[0][0][0]);
    const uint32_t bBase = (uint32_t)__cvta_generic_to_shared(&Bs[0][0][0]);
    const uint32_t aLane = aBase + (wm + (lane & 15)) * 48 + (lane & 16);
    const uint32_t bLane =
        bBase + (lane & 15) * (BROW * 2) + (wn + ((lane & 16) >> 1)) * 2;
    constexpr uint32_t AsBytes = BM * RP * 2;
    constexpr uint32_t BsBytes = GBK * BROW * 2;

    // staging: A uint2 (4 halves)/thread; B uint4 (8 halves)/thread
    const int arow = t >> 2, acol = (t & 3) * 4;
    const int bkr = t >> 4, bcol = (t & 15) * 8;

    uint2 pah;
    uint4 pbu;
    auto ldg = [&](int k0) {
        int gr = bm + arow;
        pah = (gr < M) ? *(const uint2*)(A + (size_t)gr * K + k0 + acol)
                       : make_uint2(0u, 0u);
        pbu = *(const uint4*)(B + (size_t)(k0 + bkr) * N + bn + bcol);
    };
    auto sts = [&](int s) {
        *(uint2*)&As[s][arow][acol] = pah;
        *(uint4*)&Bs[s][bkr][bcol] = pbu;
    };

    float acc[MI][NJ][4];
#pragma unroll
    for (int i = 0; i < MI; i++)
#pragma unroll
        for (int j = 0; j < NJ; j++)
#pragma unroll
            for (int r = 0; r < 4; r++) acc[i][j][r] = 0.f;

    const int nIter = K / GBK;
    ldg(0);
    sts(0);
    __syncthreads();

    for (int it = 0; it < nIter; it++) {
        const int s = it & 1;
        if (it + 1 < nIter) ldg((it + 1) * GBK);
        const uint32_t aBuf = aLane + s * AsBytes;
        const uint32_t bBuf = bLane + s * BsBytes;
        uint32_t af[MI][4], bf[NJ][2];
#pragma unroll
        for (int i = 0; i < MI; i++)
            ldsm_x4(af[i][0], af[i][1], af[i][2], af[i][3], aBuf + i * 16 * 48);
#pragma unroll
        for (int j2 = 0; j2 < NJ / 2; j2++)
            ldsm_x4_trans(bf[2 * j2][0], bf[2 * j2][1], bf[2 * j2 + 1][0],
                          bf[2 * j2 + 1][1], bBuf + j2 * 32);
#pragma unroll
        for (int i = 0; i < MI; i++)
#pragma unroll
            for (int j = 0; j < NJ; j++) mma_f16(acc[i][j], af[i], bf[j]);
        if (it + 1 < nIter) {
            sts(s ^ 1);
            __syncthreads();
        }
    }

    // epilogue: half store + fused partial dots into as/ad via atomics
#pragma unroll
    for (int i = 0; i < MI; i++) {
        int r0 = bm + wm + i * 16 + g;
        int r1 = r0 + 8;
        float s0 = 0.f, d0 = 0.f, s1 = 0.f, d1 = 0.f;
#pragma unroll
        for (int j = 0; j < NJ; j++) {
            int c = bn + wn + j * 8 + 2 * t4;
            float a0 = av[c], a1 = av[c + 1];
            float e0 = dv[c], e1 = dv[c + 1];
            s0 += acc[i][j][0] * a0 + acc[i][j][1] * a1;
            d0 += acc[i][j][0] * e0 + acc[i][j][1] * e1;
            s1 += acc[i][j][2] * a0 + acc[i][j][3] * a1;
            d1 += acc[i][j][2] * e0 + acc[i][j][3] * e1;
            if (r0 < M)
                *(__half2*)(Ch + (size_t)r0 * N + c) =
                    __floats2half2_rn(acc[i][j][0], acc[i][j][1]);
            if (r1 < M)
                *(__half2*)(Ch + (size_t)r1 * N + c) =
                    __floats2half2_rn(acc[i][j][2], acc[i][j][3]);
        }
#pragma unroll
        for (int o = 1; o < 4; o <<= 1) {
            s0 += __shfl_xor_sync(~0u, s0, o);
            d0 += __shfl_xor_sync(~0u, d0, o);
            s1 += __shfl_xor_sync(~0u, s1, o);
            d1 += __shfl_xor_sync(~0u, d1, o);
        }
        if (t4 == 0) {
            if (r0 < M) {
                atomicAdd(&as_out[r0], s0);
                atomicAdd(&ad_out[r0], d0);
            }
            if (r1 < M) {
                atomicAdd(&as_out[r1], s1);
                atomicAdd(&ad_out[r1], d1);
            }
        }
    }
}

__device__ __forceinline__ float leaky(float x) {
    return fmaxf(x, NEG_SLOPE * x);
}

// -------- warp-per-node fused alpha + softmax + fp16 gather aggregation ----
// C==256 -> layer 1 (aev = edge.y), C==128 -> layer 2 (aev = edge.z)
template <int C, bool RELU, typename TOUT>
__global__ void aggregate_kernel(const __half* __restrict__ hh,
                                 const float* __restrict__ bias,
                                 TOUT* __restrict__ out,
                                 const float* __restrict__ asv,
                                 const float* __restrict__ adv, int N) {
    int warp = (blockIdx.x * blockDim.x + threadIdx.x) >> 5;
    int lane = threadIdx.x & 31;
    if (warp >= N) return;
    const int n = warp;
    const int rs = d_row[n], re = d_row[n + 1];
    const float adn = adv[n];
    constexpr int LAYER = (C == 256) ? 0 : 1;
    float eself = __expf(leaky(asv[n] + adn + d_loopae[LAYER]));
    // pass 1: per-edge exp(leaky(logit)), lane-parallel; logits are O(1)
    float ssum = 0.f;
    for (int j = rs + lane; j < re; j += 32) {
        int4 e4 = d_edge[j];
        float aevj = (C == 256) ? __int_as_float(e4.y) : __int_as_float(e4.z);
        float ex = __expf(leaky(asv[e4.x] + aevj + adn));
        d_alpha[j] = ex;
        ssum += ex;
    }
    for (int o = 16; o; o >>= 1) ssum += __shfl_xor_sync(~0u, ssum, o);
    __syncwarp();  // fence d_alpha stores before cross-lane reads
    float inv = 1.f / (ssum + eself);

    constexpr int NH2 = C / 64;  // half2 per lane (4 for C=256, 2 for C=128)
    float acc[2 * NH2];
    union U4 { uint4 v; __half2 h2[4]; };
    union U2 { uint2 v; __half2 h2[2]; };

    auto accum = [&](int s, float w) {
        if constexpr (C == 256) {
            U4 r; r.v = ((const uint4*)(hh + (size_t)s * C))[lane];
#pragma unroll
            for (int k = 0; k < 4; k++) {
                float2 f = __half22float2(r.h2[k]);
                acc[2 * k] += w * f.x;
                acc[2 * k + 1] += w * f.y;
            }
        } else {
            U2 r; r.v = ((const uint2*)(hh + (size_t)s * C))[lane];
#pragma unroll
            for (int k = 0; k < 2; k++) {
                float2 f = __half22float2(r.h2[k]);
                acc[2 * k] += w * f.x;
                acc[2 * k + 1] += w * f.y;
            }
        }
    };

#pragma unroll
    for (int k = 0; k < 2 * NH2; k++) acc[k] = 0.f;
    accum(n, eself * inv);  // self loop

    // 4x unrolled edge loop -> gather MLP=4
    int j = rs;
    for (; j + 4 <= re; j += 4) {
        float w0 = d_alpha[j] * inv, w1 = d_alpha[j + 1] * inv;
        float w2 = d_alpha[j + 2] * inv, w3 = d_alpha[j + 3] * inv;
        int s0 = d_edge[j].x, s1 = d_edge[j + 1].x;
        int s2 = d_edge[j + 2].x, s3 = d_edge[j + 3].x;
        if constexpr (C == 256) {
            U4 r0, r1, r2, r3;
            r0.v = ((const uint4*)(hh + (size_t)s0 * C))[lane];
            r1.v = ((const uint4*)(hh + (size_t)s1 * C))[lane];
            r2.v = ((const uint4*)(hh + (size_t)s2 * C))[lane];
            r3.v = ((const uint4*)(hh + (size_t)s3 * C))[lane];
#pragma unroll
            for (int k = 0; k < 4; k++) {
                float2 f0 = __half22float2(r0.h2[k]);
                float2 f1 = __half22float2(r1.h2[k]);
                float2 f2 = __half22float2(r2.h2[k]);
                float2 f3 = __half22float2(r3.h2[k]);
                acc[2 * k] += w0 * f0.x + w1 * f1.x + w2 * f2.x + w3 * f3.x;
                acc[2 * k + 1] +=
                    w0 * f0.y + w1 * f1.y + w2 * f2.y + w3 * f3.y;
            }
        } else {
            U2 r0, r1, r2, r3;
            r0.v = ((const uint2*)(hh + (size_t)s0 * C))[lane];
            r1.v = ((const uint2*)(hh + (size_t)s1 * C))[lane];
            r2.v = ((const uint2*)(hh + (size_t)s2 * C))[lane];
            r3.v = ((const uint2*)(hh + (size_t)s3 * C))[lane];
#pragma unroll
            for (int k = 0; k < 2; k++) {
                float2 f0 = __half22float2(r0.h2[k]);
                float2 f1 = __half22float2(r1.h2[k]);
                float2 f2 = __half22float2(r2.h2[k]);
                float2 f3 = __half22float2(r3.h2[k]);
                acc[2 * k] += w0 * f0.x + w1 * f1.x + w2 * f2.x + w3 * f3.x;
                acc[2 * k + 1] +=
                    w0 * f0.y + w1 * f1.y + w2 * f2.y + w3 * f3.y;
            }
        }
    }
    for (; j < re; j++) accum(d_edge[j].x, d_alpha[j] * inv);

    // write out: lane owns columns [lane*2*NH2, +2*NH2)
    const int base = lane * 2 * NH2;
    const float* bp = bias + base;
    float vv[2 * NH2];
#pragma unroll
    for (int k = 0; k < 2 * NH2; k++) {
        vv[k] = acc[k] + bp[k];
        if (RELU) vv[k] = fmaxf(vv[k], 0.f);
    }
    if constexpr (sizeof(TOUT) == 2) {
        __half2* op = (__half2*)((__half*)out + (size_t)n * C + base);
#pragma unroll
        for (int k = 0; k < NH2; k++)
            op[k] = __floats2half2_rn(vv[2 * k], vv[2 * k + 1]);
    } else {
        float* op = (float*)out + (size_t)n * C + base;
#pragma unroll
        for (int k = 0; k < 2 * NH2; k += 4)
            *(float4*)(op + k) =
                make_float4(vv[k], vv[k + 1], vv[k + 2], vv[k + 3]);
    }
}

// ---------------- launch ----------------------------------------------------
extern "C" void kernel_launch(void* const* d_in, const int* in_sizes, int n_in,
                              void* d_out, int out_size) {
    const float* x   = (const float*)d_in[0];
    const int*   ei  = (const int*)d_in[1];
    const float* ea  = (const float*)d_in[2];
    const float* W1  = (const float*)d_in[3];
    const float* We1 = (const float*)d_in[4];
    const float* as1 = (const float*)d_in[5];
    const float* ad1 = (const float*)d_in[6];
    const float* ae1 = (const float*)d_in[7];
    const float* b1  = (const float*)d_in[8];
    const float* W2  = (const float*)d_in[9];
    const float* We2 = (const float*)d_in[10];
    const float* as2 = (const float*)d_in[11];
    const float* ad2 = (const float*)d_in[12];
    const float* ae2 = (const float*)d_in[13];
    const float* b2  = (const float*)d_in[14];
    float* out = (float*)d_out;

    const int E = in_sizes[2] / ED;
    const int N = in_sizes[0] / CIN;
    const int* srcp = ei;
    const int* dstp = ei + E;

    void* p;
    cudaGetSymbolAddress(&p, d_xh);   __half* xhp  = (__half*)p;
    cudaGetSymbolAddress(&p, d_w1h);  __half* w1hp = (__half*)p;
    cudaGetSymbolAddress(&p, d_w2h);  __half* w2hp = (__half*)p;
    cudaGetSymbolAddress(&p, d_hh);   __half* hhp  = (__half*)p;
    cudaGetSymbolAddress(&p, d_hid);  __half* hidp = (__half*)p;
    cudaGetSymbolAddress(&p, d_as1);  float* as1p  = (float*)p;
    cudaGetSymbolAddress(&p, d_ad1);  float* ad1p  = (float*)p;
    cudaGetSymbolAddress(&p, d_as2);  float* as2p  = (float*)p;
    cudaGetSymbolAddress(&p, d_ad2);  float* ad2p  = (float*)p;

    const int TPB = 256;
    const int warpsPerBlock = TPB / 32;
    const int nodeBlocks = (N + warpsPerBlock - 1) / warpsPerBlock;
    const int mBlocks = (N + 63) / 64;
    const int scanBlocks = (N + SCAN_TPB - 1) / SCAN_TPB;  // 196 <= 256

    // structure build prologue
    prep_kernel<<<256, 512>>>(x, W1, W2, N);
    vcomp_kernel<<<1, 512>>>(We1, ae1, We2, ae2);
    hist_kernel<<<512, TPB>>>(dstp, ea, E);

    // multi-block scan (replaces 78us single-block scan)
    scan_p1_kernel<<<scanBlocks, SCAN_TPB>>>(N);
    scan_p2_kernel<<<1, SCAN_TPB>>>(scanBlocks, N, 1.f / (float)E);
    scan_p3_kernel<<<scanBlocks, SCAN_TPB>>>(N);

    // CSR scatter
    scatter_kernel<<<512, TPB>>>(srcp, dstp, E);

    // layer-1 GEMM (all-fp16 inputs, +fused dots)
    mma_gemm_kernel<<<dim3(CHID / 128, mBlocks), 256>>>(
        xhp, w1hp, hhp, as1, ad1, as1p, ad1p, N, CHID, CIN);

    // layer-1 fused alpha+softmax+aggregate -> fp16 hidden
    aggregate_kernel<CHID, true, __half><<<nodeBlocks, TPB>>>(
        hhp, b1, hidp, as1p, ad1p, N);

    // layer-2 GEMM (fp16 inputs, +fused dots)
    mma_gemm_kernel<<<dim3(COUT / 128, mBlocks), 256>>>(
        hidp, w2hp, hhp, as2, ad2, as2p, ad2p, N, COUT, CHID);

    // layer-2 fused aggregate -> fp32 output
    aggregate_kernel<COUT, false, float><<<nodeBlocks, TPB>>>(
        hhp, b2, out, as2p, ad2p, N);
}